// round 2
// baseline (speedup 1.0000x reference)
#include <cuda_runtime.h>
#include <math.h>

// ---------------------------------------------------------------------------
// GAT_23888608101379: 3-layer GAT + mean pool + linear head.
// Pipeline per launch (all default-stream, graph-capturable, alloc-free):
//   0. detect edge_index dtype (int64 vs int32) -> g_is64
//   1. build CSR by dst (histogram, single-block scan, scatter)   [once]
//   2. per layer: SGEMM -> alpha dot -> init -> edge max -> edge exp/sum
//                 -> CSR gather aggregate (+bias, +ReLU)
//   3. mean pool -> 64x64 head
// ---------------------------------------------------------------------------

#define MAXN 50000
#define MAXE 800000
#define MAXET (MAXE + MAXN)

__device__ int   g_is64;
__device__ float g_bufA[MAXN * 256];   // GEMM output h
__device__ float g_bufB[MAXN * 256];   // layer output / next layer input
__device__ float g_as[MAXN * 4];
__device__ float g_ad[MAXN * 4];
__device__ float g_m[MAXN * 4];
__device__ float g_den[MAXN * 4];
__device__ float g_w[MAXET * 4];       // exp(e - m) per (edge, head)
__device__ int   g_rowptr[MAXN + 1];
__device__ int   g_cursor[MAXN];
__device__ int   g_csr_src[MAXET];
__device__ int   g_csr_eid[MAXET];
__device__ float g_pool[64];

// ---------------------------------------------------------------------------

__global__ void detect_kernel(const void* ei, int n) {
    if (blockIdx.x == 0 && threadIdx.x == 0) {
        const long long* p = (const long long*)ei;
        int ok = 1;
        for (int i = 0; i < 64; i++) {
            long long v = p[i];
            if (v < 0 || v >= (long long)n) { ok = 0; break; }
        }
        g_is64 = ok;
    }
}

__device__ __forceinline__ void get_edge(const void* ei, int is64, int E, int e,
                                         int& src, int& dst) {
    if (e < E) {
        if (is64) {
            const long long* p = (const long long*)ei;
            src = (int)p[e];
            dst = (int)p[E + e];
        } else {
            const int* p = (const int*)ei;
            src = p[e];
            dst = p[E + e];
        }
    } else {            // self loop
        src = e - E;
        dst = src;
    }
}

__global__ void fill_i32(int* p, int v, int n) {
    int i = blockIdx.x * blockDim.x + threadIdx.x;
    if (i < n) p[i] = v;
}

__global__ void fill_f32(float* p, float v, int n) {
    int i = blockIdx.x * blockDim.x + threadIdx.x;
    if (i < n) p[i] = v;
}

__global__ void init_md(float* m, float* den, int n) {
    int i = blockIdx.x * blockDim.x + threadIdx.x;
    if (i < n) { m[i] = -INFINITY; den[i] = 0.0f; }
}

__global__ void hist_kernel(const void* ei, int E, int n) {
    int is64 = g_is64;
    int et = E + n;
    for (int e = blockIdx.x * blockDim.x + threadIdx.x; e < et;
         e += gridDim.x * blockDim.x) {
        int src, dst;
        get_edge(ei, is64, E, e, src, dst);
        atomicAdd(&g_cursor[dst], 1);
    }
}

// single-block inclusive-scan over counts -> exclusive rowptr
__global__ void scan_kernel(int n) {
    __shared__ int sh[1024];
    __shared__ int carry;
    int tid = threadIdx.x;
    if (tid == 0) { carry = 0; g_rowptr[0] = 0; }
    __syncthreads();
    for (int base = 0; base < n; base += 1024) {
        int i = base + tid;
        int v = (i < n) ? g_cursor[i] : 0;
        sh[tid] = v;
        __syncthreads();
        for (int off = 1; off < 1024; off <<= 1) {
            int t = 0;
            if (tid >= off) t = sh[tid - off];
            __syncthreads();
            sh[tid] += t;
            __syncthreads();
        }
        if (i < n) g_rowptr[i + 1] = carry + sh[tid];
        __syncthreads();
        if (tid == 0) carry += sh[1023];
        __syncthreads();
    }
}

__global__ void copy_cursor(int n) {
    int i = blockIdx.x * blockDim.x + threadIdx.x;
    if (i < n) g_cursor[i] = g_rowptr[i];
}

__global__ void scatter_kernel(const void* ei, int E, int n) {
    int is64 = g_is64;
    int et = E + n;
    for (int e = blockIdx.x * blockDim.x + threadIdx.x; e < et;
         e += gridDim.x * blockDim.x) {
        int src, dst;
        get_edge(ei, is64, E, e, src, dst);
        int pos = atomicAdd(&g_cursor[dst], 1);
        g_csr_src[pos] = src;
        g_csr_eid[pos] = e;
    }
}

// ---------------------------------------------------------------------------
// SGEMM: C[n,M] = A[n,K] @ B[K,M].  BM=BN=64, BK=16, 256 thr, 4x4 per thread.
// K in {128,256} (mult of 16), M in {64,256} (mult of 64).
// ---------------------------------------------------------------------------
__global__ void sgemm(const float* __restrict__ A, const float* __restrict__ B,
                      float* __restrict__ C, int n, int K, int M) {
    __shared__ float As[16][68];   // [k][row], padded
    __shared__ float Bs[16][64];   // [k][col]
    int tid = threadIdx.x;
    int tx = tid & 15, ty = tid >> 4;
    int rowBase = blockIdx.y * 64;
    int colBase = blockIdx.x * 64;

    int arow = tid >> 2;
    int acol = (tid & 3) * 4;
    int brow = tid >> 4;
    int bcol = (tid & 15) * 4;

    float acc[4][4] = {};
    for (int k0 = 0; k0 < K; k0 += 16) {
        float4 av = make_float4(0, 0, 0, 0);
        if (rowBase + arow < n)
            av = *(const float4*)&A[(size_t)(rowBase + arow) * K + k0 + acol];
        As[acol + 0][arow] = av.x;
        As[acol + 1][arow] = av.y;
        As[acol + 2][arow] = av.z;
        As[acol + 3][arow] = av.w;
        float4 bv = *(const float4*)&B[(size_t)(k0 + brow) * M + colBase + bcol];
        *(float4*)&Bs[brow][bcol] = bv;
        __syncthreads();
#pragma unroll
        for (int k = 0; k < 16; k++) {
            float a[4], b[4];
#pragma unroll
            for (int i = 0; i < 4; i++) a[i] = As[k][ty * 4 + i];
#pragma unroll
            for (int j = 0; j < 4; j++) b[j] = Bs[k][tx * 4 + j];
#pragma unroll
            for (int i = 0; i < 4; i++)
#pragma unroll
                for (int j = 0; j < 4; j++)
                    acc[i][j] = fmaf(a[i], b[j], acc[i][j]);
        }
        __syncthreads();
    }
#pragma unroll
    for (int i = 0; i < 4; i++) {
        int r = rowBase + ty * 4 + i;
        if (r < n) {
            float4 o = make_float4(acc[i][0], acc[i][1], acc[i][2], acc[i][3]);
            *(float4*)&C[(size_t)r * M + colBase + tx * 4] = o;
        }
    }
}

// ---------------------------------------------------------------------------
// alpha_s[n,h] = sum_c h[n,h,c]*a_s[h,c]; same for alpha_d. Block = H*64 thr.
// ---------------------------------------------------------------------------
__global__ void alpha_kernel(const float* __restrict__ Hm,
                             const float* __restrict__ avs,
                             const float* __restrict__ avd,
                             int H) {
    int node = blockIdx.x;
    int t = threadIdx.x;           // 0..H*64-1
    int h = t >> 6;
    int M = H * 64;
    float v = Hm[(size_t)node * M + t];
    float ps = v * avs[t];
    float pd = v * avd[t];
#pragma unroll
    for (int off = 16; off; off >>= 1) {
        ps += __shfl_down_sync(0xffffffffu, ps, off);
        pd += __shfl_down_sync(0xffffffffu, pd, off);
    }
    __shared__ float ss[8], sd[8];
    int w = t >> 5;
    if ((t & 31) == 0) { ss[w] = ps; sd[w] = pd; }
    __syncthreads();
    if ((t & 63) == 0) {
        g_as[node * H + h] = ss[h * 2] + ss[h * 2 + 1];
        g_ad[node * H + h] = sd[h * 2] + sd[h * 2 + 1];
    }
}

// ---------------------------------------------------------------------------

__device__ __forceinline__ void atomicMaxF(float* addr, float v) {
    if (v >= 0.0f)
        atomicMax((int*)addr, __float_as_int(v));
    else
        atomicMin((unsigned int*)addr, (unsigned int)__float_as_int(v));
}

__global__ void edge_max(const void* ei, int E, int n, int H) {
    int is64 = g_is64;
    int et = E + n;
    for (int e = blockIdx.x * blockDim.x + threadIdx.x; e < et;
         e += gridDim.x * blockDim.x) {
        int src, dst;
        get_edge(ei, is64, E, e, src, dst);
#pragma unroll 4
        for (int h = 0; h < H; h++) {
            float v = g_as[src * H + h] + g_ad[dst * H + h];
            v = (v > 0.0f) ? v : 0.2f * v;
            atomicMaxF(&g_m[dst * H + h], v);
        }
    }
}

__global__ void edge_exp(const void* ei, int E, int n, int H) {
    int is64 = g_is64;
    int et = E + n;
    for (int e = blockIdx.x * blockDim.x + threadIdx.x; e < et;
         e += gridDim.x * blockDim.x) {
        int src, dst;
        get_edge(ei, is64, E, e, src, dst);
#pragma unroll 4
        for (int h = 0; h < H; h++) {
            float v = g_as[src * H + h] + g_ad[dst * H + h];
            v = (v > 0.0f) ? v : 0.2f * v;
            float ex = expf(v - g_m[dst * H + h]);
            g_w[e * H + h] = ex;
            atomicAdd(&g_den[dst * H + h], ex);
        }
    }
}

// ---------------------------------------------------------------------------
// CSR gather aggregation: out[dst, t] = (sum_e w[e,h]*H[src_e, t]) / den + b,
// optional ReLU. One block per dst node, H*64 threads.
// ---------------------------------------------------------------------------
template <int H, int RELU>
__global__ void aggregate(const float* __restrict__ Hm,
                          const float* __restrict__ bias,
                          float* __restrict__ out) {
    const int M = H * 64;
    int dst = blockIdx.x;
    int t = threadIdx.x;
    int h = t >> 6;
    int beg = g_rowptr[dst];
    int end = g_rowptr[dst + 1];
    float acc = 0.0f;
    int j = beg;
    if (j < end) {
        int src = __ldg(&g_csr_src[j]);
        int eid = __ldg(&g_csr_eid[j]);
        float w = __ldg(&g_w[eid * H + h]);
        const float* hp = &Hm[(size_t)src * M + t];
        for (; j + 1 < end; j++) {
            int src2 = __ldg(&g_csr_src[j + 1]);
            int eid2 = __ldg(&g_csr_eid[j + 1]);
            float w2 = __ldg(&g_w[eid2 * H + h]);
            acc = fmaf(w, __ldg(hp), acc);
            w = w2;
            hp = &Hm[(size_t)src2 * M + t];
        }
        acc = fmaf(w, __ldg(hp), acc);
    }
    float den = g_den[dst * H + h] + 1e-16f;
    float o = acc / den + bias[t];
    if (RELU) o = fmaxf(o, 0.0f);
    out[(size_t)dst * M + t] = o;
}

// ---------------------------------------------------------------------------

__global__ void pool_kernel(const float* __restrict__ X, int n) {
    int c = threadIdx.x;   // 64
    float s = 0.0f;
    for (int r = blockIdx.x; r < n; r += gridDim.x)
        s += X[(size_t)r * 64 + c];
    atomicAdd(&g_pool[c], s);
}

__global__ void head_kernel(const float* __restrict__ hw,
                            const float* __restrict__ hb,
                            float* __restrict__ out, int n) {
    int j = threadIdx.x;   // 64
    float inv = 1.0f / (float)n;
    float s = 0.0f;
#pragma unroll
    for (int c = 0; c < 64; c++)
        s = fmaf(g_pool[c] * inv, hw[c * 64 + j], s);
    out[j] = s + hb[j];
}

// ---------------------------------------------------------------------------

extern "C" void kernel_launch(void* const* d_in, const int* in_sizes, int n_in,
                              void* d_out, int out_size) {
    const float* x   = (const float*)d_in[0];
    const void*  ei  = d_in[1];
    const float* W0  = (const float*)d_in[2];
    const float* a0s = (const float*)d_in[3];
    const float* a0d = (const float*)d_in[4];
    const float* b0  = (const float*)d_in[5];
    const float* W1  = (const float*)d_in[6];
    const float* a1s = (const float*)d_in[7];
    const float* a1d = (const float*)d_in[8];
    const float* b1  = (const float*)d_in[9];
    const float* W2  = (const float*)d_in[10];
    const float* a2s = (const float*)d_in[11];
    const float* a2d = (const float*)d_in[12];
    const float* b2  = (const float*)d_in[13];
    const float* hw  = (const float*)d_in[14];
    const float* hb  = (const float*)d_in[15];
    float* out = (float*)d_out;

    int n = in_sizes[0] / 128;
    int E = in_sizes[1] / 2;
    int et = E + n;

    float *bufA, *bufB, *pool, *gm, *gden;
    int *gcursor;
    cudaGetSymbolAddress((void**)&bufA, g_bufA);
    cudaGetSymbolAddress((void**)&bufB, g_bufB);
    cudaGetSymbolAddress((void**)&pool, g_pool);
    cudaGetSymbolAddress((void**)&gm, g_m);
    cudaGetSymbolAddress((void**)&gden, g_den);
    cudaGetSymbolAddress((void**)&gcursor, g_cursor);

    int eblocks = (et + 255) / 256;
    if (eblocks > 4096) eblocks = 4096;

    // 0. dtype detection
    detect_kernel<<<1, 32>>>(ei, n);

    // 1. CSR build (dst-indexed)
    fill_i32<<<(n + 255) / 256, 256>>>(gcursor, 0, n);
    hist_kernel<<<eblocks, 256>>>(ei, E, n);
    scan_kernel<<<1, 1024>>>(n);
    copy_cursor<<<(n + 255) / 256, 256>>>(n);
    scatter_kernel<<<eblocks, 256>>>(ei, E, n);

    dim3 ggrid((256 + 63) / 64, (n + 63) / 64);

    // ---- Layer 0: 128 -> (4,64) ----
    sgemm<<<dim3(4, (n + 63) / 64), 256>>>(x, W0, bufA, n, 128, 256);
    alpha_kernel<<<n, 256>>>(bufA, a0s, a0d, 4);
    init_md<<<(n * 4 + 255) / 256, 256>>>(gm, gden, n * 4);
    edge_max<<<eblocks, 256>>>(ei, E, n, 4);
    edge_exp<<<eblocks, 256>>>(ei, E, n, 4);
    aggregate<4, 1><<<n, 256>>>(bufA, b0, bufB);

    // ---- Layer 1: 256 -> (4,64) ----
    sgemm<<<dim3(4, (n + 63) / 64), 256>>>(bufB, W1, bufA, n, 256, 256);
    alpha_kernel<<<n, 256>>>(bufA, a1s, a1d, 4);
    init_md<<<(n * 4 + 255) / 256, 256>>>(gm, gden, n * 4);
    edge_max<<<eblocks, 256>>>(ei, E, n, 4);
    edge_exp<<<eblocks, 256>>>(ei, E, n, 4);
    aggregate<4, 1><<<n, 256>>>(bufA, b1, bufB);

    // ---- Layer 2: 256 -> (1,64) ----
    sgemm<<<dim3(1, (n + 63) / 64), 256>>>(bufB, W2, bufA, n, 256, 64);
    alpha_kernel<<<n, 64>>>(bufA, a2s, a2d, 1);
    init_md<<<(n * 1 + 255) / 256, 256>>>(gm, gden, n * 1);
    edge_max<<<eblocks, 256>>>(ei, E, n, 1);
    edge_exp<<<eblocks, 256>>>(ei, E, n, 1);
    aggregate<1, 0><<<n, 64>>>(bufA, b2, bufB);

    // ---- Mean pool + head ----
    fill_f32<<<1, 64>>>(pool, 0.0f, 64);
    pool_kernel<<<128, 64>>>(bufB, n);
    head_kernel<<<1, 64>>>(hw, hb, out, n);
}

// round 7
// speedup vs baseline: 1.4153x; 1.4153x over previous
#include <cuda_runtime.h>
#include <math.h>

// ---------------------------------------------------------------------------
// GAT_23888608101379: 3-layer GAT + mean pool + linear head.
//   - CSR build (histogram, parallel 2-level scan, scatter)
//   - per layer: SGEMM (128x64 dbuf, fused alpha epilogue)
//                -> fused softmax+aggregate (CSR, no atomics)
//   - mean pool -> 64x64 head
// ---------------------------------------------------------------------------

#define MAXN 50000
#define MAXE 800000
#define MAXET (MAXE + MAXN)
#define NB_MAX 64

__device__ int   g_is64;
__device__ float g_bufA[MAXN * 256];   // GEMM output h
__device__ float g_bufB[MAXN * 256];   // layer output / next input
__device__ float g_as[MAXN * 4];
__device__ float g_ad[MAXN * 4];
__device__ int   g_rowptr[MAXN + 1];
__device__ int   g_cursor[MAXN];
__device__ int   g_csr_src[MAXET];
__device__ int   g_aux[NB_MAX];
__device__ float g_pool[64];

// ---------------------------------------------------------------------------

__global__ void detect_kernel(const void* ei, int n) {
    if (blockIdx.x == 0 && threadIdx.x == 0) {
        const long long* p = (const long long*)ei;
        int ok = 1;
        for (int i = 0; i < 64; i++) {
            long long v = p[i];
            if (v < 0 || v >= (long long)n) { ok = 0; break; }
        }
        g_is64 = ok;
    }
}

__device__ __forceinline__ void get_edge(const void* ei, int is64, int E, int e,
                                         int& src, int& dst) {
    if (e < E) {
        if (is64) {
            const long long* p = (const long long*)ei;
            src = (int)p[e];
            dst = (int)p[E + e];
        } else {
            const int* p = (const int*)ei;
            src = p[e];
            dst = p[E + e];
        }
    } else {            // self loop
        src = e - E;
        dst = src;
    }
}

__global__ void fill_i32(int* p, int v, int n) {
    int i = blockIdx.x * blockDim.x + threadIdx.x;
    if (i < n) p[i] = v;
}

__global__ void fill_f32(float* p, float v, int n) {
    int i = blockIdx.x * blockDim.x + threadIdx.x;
    if (i < n) p[i] = v;
}

__global__ void hist_kernel(const void* ei, int E, int n) {
    int is64 = g_is64;
    int et = E + n;
    for (int e = blockIdx.x * blockDim.x + threadIdx.x; e < et;
         e += gridDim.x * blockDim.x) {
        int src, dst;
        get_edge(ei, is64, E, e, src, dst);
        atomicAdd(&g_cursor[dst], 1);
    }
}

// ---- 2-level parallel exclusive scan of counts -> rowptr ----
__global__ void scan_local(int n) {           // grid = nb, block = 1024
    __shared__ int sh[1024];
    int b = blockIdx.x, tid = threadIdx.x;
    int i = b * 1024 + tid;
    int v = (i < n) ? g_cursor[i] : 0;
    sh[tid] = v;
    __syncthreads();
    for (int off = 1; off < 1024; off <<= 1) {
        int t = (tid >= off) ? sh[tid - off] : 0;
        __syncthreads();
        sh[tid] += t;
        __syncthreads();
    }
    if (i < n) g_rowptr[i + 1] = sh[tid];
    if (tid == 1023) g_aux[b] = sh[1023];
}

__global__ void scan_aux(int nb) {            // 1 thread, nb <= 64
    if (threadIdx.x == 0) {
        int s = 0;
        for (int b = 0; b < nb; b++) { int v = g_aux[b]; g_aux[b] = s; s += v; }
        g_rowptr[0] = 0;
    }
}

__global__ void scan_add(int n) {             // grid = nb, block = 1024
    int b = blockIdx.x;
    int i = b * 1024 + threadIdx.x;
    if (i < n) g_rowptr[i + 1] += g_aux[b];
}

__global__ void copy_cursor(int n) {
    int i = blockIdx.x * blockDim.x + threadIdx.x;
    if (i < n) g_cursor[i] = g_rowptr[i];
}

__global__ void scatter_kernel(const void* ei, int E, int n) {
    int is64 = g_is64;
    int et = E + n;
    for (int e = blockIdx.x * blockDim.x + threadIdx.x; e < et;
         e += gridDim.x * blockDim.x) {
        int src, dst;
        get_edge(ei, is64, E, e, src, dst);
        int pos = atomicAdd(&g_cursor[dst], 1);
        g_csr_src[pos] = src;
    }
}

// ---------------------------------------------------------------------------
// SGEMM: C[n,M] = A[n,K] @ B[K,M].  BM=128, BN=64, BK=8, 256 thr, 8x4/thread,
// double-buffered shared memory with register prefetch.
// K mult of 8, M mult of 64. The 64-col tile of one block == one head, so the
// alpha_s/alpha_d dot-products are computed in the epilogue via 16-lane
// shuffle reductions (eliminates a separate full-matrix pass).
// ---------------------------------------------------------------------------
__global__ __launch_bounds__(256)
void sgemm(const float* __restrict__ A, const float* __restrict__ B,
           float* __restrict__ C, int n, int K, int M,
           const float* __restrict__ avs, const float* __restrict__ avd,
           int H) {
    __shared__ float As[2][8][128];
    __shared__ float Bs[2][8][64];
    int tid = threadIdx.x;
    int rowBase = blockIdx.y * 128;
    int colBase = blockIdx.x * 64;
    int head = colBase >> 6;

    int arow = tid >> 1;            // 0..127
    int acol = (tid & 1) * 4;       // 0 or 4
    int brow = tid >> 5;            // 0..7
    int bcol = (tid & 31) * 2;      // 0..62

    int tx = tid & 15;              // col group (4 cols)
    int ty = tid >> 4;              // row group (8 rows)

    float4 aReg = make_float4(0, 0, 0, 0);
    float2 bReg;
    if (rowBase + arow < n)
        aReg = *(const float4*)&A[(size_t)(rowBase + arow) * K + acol];
    bReg = *(const float2*)&B[(size_t)brow * M + colBase + bcol];
    As[0][acol + 0][arow] = aReg.x;
    As[0][acol + 1][arow] = aReg.y;
    As[0][acol + 2][arow] = aReg.z;
    As[0][acol + 3][arow] = aReg.w;
    Bs[0][brow][bcol] = bReg.x;
    Bs[0][brow][bcol + 1] = bReg.y;
    __syncthreads();

    float acc[8][4] = {};
    int nk = K >> 3;
    for (int t = 0; t < nk; t++) {
        int cur = t & 1, nxt = cur ^ 1;
        if (t + 1 < nk) {
            int k0 = (t + 1) << 3;
            aReg = make_float4(0, 0, 0, 0);
            if (rowBase + arow < n)
                aReg = *(const float4*)&A[(size_t)(rowBase + arow) * K + k0 + acol];
            bReg = *(const float2*)&B[(size_t)(k0 + brow) * M + colBase + bcol];
        }
#pragma unroll
        for (int k = 0; k < 8; k++) {
            float a[8], b[4];
#pragma unroll
            for (int i = 0; i < 8; i++) a[i] = As[cur][k][ty * 8 + i];
#pragma unroll
            for (int j = 0; j < 4; j++) b[j] = Bs[cur][k][tx * 4 + j];
#pragma unroll
            for (int i = 0; i < 8; i++)
#pragma unroll
                for (int j = 0; j < 4; j++)
                    acc[i][j] = fmaf(a[i], b[j], acc[i][j]);
        }
        if (t + 1 < nk) {
            As[nxt][acol + 0][arow] = aReg.x;
            As[nxt][acol + 1][arow] = aReg.y;
            As[nxt][acol + 2][arow] = aReg.z;
            As[nxt][acol + 3][arow] = aReg.w;
            Bs[nxt][brow][bcol] = bReg.x;
            Bs[nxt][brow][bcol + 1] = bReg.y;
        }
        __syncthreads();
    }

    // ---- store C tile ----
#pragma unroll
    for (int i = 0; i < 8; i++) {
        int r = rowBase + ty * 8 + i;
        if (r < n) {
            float4 o = make_float4(acc[i][0], acc[i][1], acc[i][2], acc[i][3]);
            *(float4*)&C[(size_t)r * M + colBase + tx * 4] = o;
        }
    }

    // ---- fused alpha epilogue: per-row dot with a_s / a_d over this head ----
    float as_l[4], ad_l[4];
#pragma unroll
    for (int j = 0; j < 4; j++) {
        as_l[j] = __ldg(&avs[head * 64 + tx * 4 + j]);
        ad_l[j] = __ldg(&avd[head * 64 + tx * 4 + j]);
    }
#pragma unroll
    for (int i = 0; i < 8; i++) {
        float ps = 0.0f, pd = 0.0f;
#pragma unroll
        for (int j = 0; j < 4; j++) {
            ps = fmaf(acc[i][j], as_l[j], ps);
            pd = fmaf(acc[i][j], ad_l[j], pd);
        }
        // reduce over the 16-lane tx group (xor offsets stay within half-warp)
#pragma unroll
        for (int o = 8; o; o >>= 1) {
            ps += __shfl_xor_sync(0xffffffffu, ps, o);
            pd += __shfl_xor_sync(0xffffffffu, pd, o);
        }
        int r = rowBase + ty * 8 + i;
        if (tx == 0 && r < n) {
            g_as[r * H + head] = ps;
            g_ad[r * H + head] = pd;
        }
    }
}

// ---------------------------------------------------------------------------
// Fused softmax + aggregation over CSR row of dst.
// Block = H*64 threads per dst node.
//   Phase A: warp h computes per-head max and denom over the row (no atomics).
//   Phase B: chunks of 32 edges; warp h writes w[i][h] to smem, all threads
//            accumulate sum_i w[i][h] * Hm[src_i, t].
// out[dst,t] = acc + bias, optional ReLU.
// ---------------------------------------------------------------------------
template <int H, int RELU>
__global__ void aggregate_fused(const float* __restrict__ Hm,
                                const float* __restrict__ bias,
                                float* __restrict__ out) {
    const int M = H * 64;
    int dst = blockIdx.x;
    int t = threadIdx.x;
    int h = t >> 6;
    int lane = t & 31;
    int wid = t >> 5;
    int beg = g_rowptr[dst];
    int end = g_rowptr[dst + 1];

    __shared__ float sm_m[H];
    __shared__ float sm_inv[H];
    __shared__ int   sm_src[32];
    __shared__ float sm_w[32][H];

    float ad_h = 0.0f;
    if (wid < H) {
        ad_h = g_ad[dst * H + wid];
        float mx = -INFINITY;
        for (int j = beg + lane; j < end; j += 32) {
            float e = __ldg(&g_as[__ldg(&g_csr_src[j]) * H + wid]) + ad_h;
            e = (e > 0.0f) ? e : 0.2f * e;
            mx = fmaxf(mx, e);
        }
#pragma unroll
        for (int o = 16; o; o >>= 1)
            mx = fmaxf(mx, __shfl_xor_sync(0xffffffffu, mx, o));
        float s = 0.0f;
        for (int j = beg + lane; j < end; j += 32) {
            float e = __ldg(&g_as[__ldg(&g_csr_src[j]) * H + wid]) + ad_h;
            e = (e > 0.0f) ? e : 0.2f * e;
            s += expf(e - mx);
        }
#pragma unroll
        for (int o = 16; o; o >>= 1)
            s += __shfl_xor_sync(0xffffffffu, s, o);
        if (lane == 0) { sm_m[wid] = mx; sm_inv[wid] = 1.0f / (s + 1e-16f); }
    }
    __syncthreads();
    float m_h = 0.0f, inv_h = 0.0f;
    if (wid < H) { m_h = sm_m[wid]; inv_h = sm_inv[wid]; }

    float acc0 = 0.0f, acc1 = 0.0f;
    for (int c0 = beg; c0 < end; c0 += 32) {
        int cnt = min(32, end - c0);
        if (wid < H && lane < cnt) {
            int src = __ldg(&g_csr_src[c0 + lane]);
            if (wid == 0) sm_src[lane] = src;
            float e = __ldg(&g_as[src * H + wid]) + ad_h;
            e = (e > 0.0f) ? e : 0.2f * e;
            sm_w[lane][wid] = expf(e - m_h) * inv_h;
        }
        __syncthreads();
        int i = 0;
        for (; i + 1 < cnt; i += 2) {
            acc0 = fmaf(sm_w[i][h],     __ldg(&Hm[(size_t)sm_src[i] * M + t]),     acc0);
            acc1 = fmaf(sm_w[i + 1][h], __ldg(&Hm[(size_t)sm_src[i + 1] * M + t]), acc1);
        }
        if (i < cnt)
            acc0 = fmaf(sm_w[i][h], __ldg(&Hm[(size_t)sm_src[i] * M + t]), acc0);
        __syncthreads();
    }
    float o = acc0 + acc1 + bias[t];
    if (RELU) o = fmaxf(o, 0.0f);
    out[(size_t)dst * M + t] = o;
}

// ---------------------------------------------------------------------------

__global__ void pool_kernel(const float* __restrict__ X, int n) {
    int c = threadIdx.x;   // 64
    float s = 0.0f;
    for (int r = blockIdx.x; r < n; r += gridDim.x)
        s += X[(size_t)r * 64 + c];
    atomicAdd(&g_pool[c], s);
}

__global__ void head_kernel(const float* __restrict__ hw,
                            const float* __restrict__ hb,
                            float* __restrict__ out, int n) {
    int j = threadIdx.x;   // 64
    float inv = 1.0f / (float)n;
    float s = 0.0f;
#pragma unroll
    for (int c = 0; c < 64; c++)
        s = fmaf(g_pool[c] * inv, hw[c * 64 + j], s);
    out[j] = s + hb[j];
}

// ---------------------------------------------------------------------------

extern "C" void kernel_launch(void* const* d_in, const int* in_sizes, int n_in,
                              void* d_out, int out_size) {
    const float* x   = (const float*)d_in[0];
    const void*  ei  = d_in[1];
    const float* W0  = (const float*)d_in[2];
    const float* a0s = (const float*)d_in[3];
    const float* a0d = (const float*)d_in[4];
    const float* b0  = (const float*)d_in[5];
    const float* W1  = (const float*)d_in[6];
    const float* a1s = (const float*)d_in[7];
    const float* a1d = (const float*)d_in[8];
    const float* b1  = (const float*)d_in[9];
    const float* W2  = (const float*)d_in[10];
    const float* a2s = (const float*)d_in[11];
    const float* a2d = (const float*)d_in[12];
    const float* b2  = (const float*)d_in[13];
    const float* hw  = (const float*)d_in[14];
    const float* hb  = (const float*)d_in[15];
    float* out = (float*)d_out;

    int n = in_sizes[0] / 128;
    int E = in_sizes[1] / 2;
    int et = E + n;

    float *bufA, *bufB, *pool;
    int *gcursor;
    cudaGetSymbolAddress((void**)&bufA, g_bufA);
    cudaGetSymbolAddress((void**)&bufB, g_bufB);
    cudaGetSymbolAddress((void**)&pool, g_pool);
    cudaGetSymbolAddress((void**)&gcursor, g_cursor);

    int eblocks = (et + 255) / 256;
    if (eblocks > 4096) eblocks = 4096;
    int nb = (n + 1023) / 1024;

    // 0. dtype detection
    detect_kernel<<<1, 32>>>(ei, n);

    // 1. CSR build (dst-indexed)
    fill_i32<<<(n + 255) / 256, 256>>>(gcursor, 0, n);
    hist_kernel<<<eblocks, 256>>>(ei, E, n);
    scan_local<<<nb, 1024>>>(n);
    scan_aux<<<1, 32>>>(nb);
    scan_add<<<nb, 1024>>>(n);
    copy_cursor<<<(n + 255) / 256, 256>>>(n);
    scatter_kernel<<<eblocks, 256>>>(ei, E, n);

    int gy = (n + 127) / 128;

    // ---- Layer 0: 128 -> (4,64) ----
    sgemm<<<dim3(4, gy), 256>>>(x, W0, bufA, n, 128, 256, a0s, a0d, 4);
    aggregate_fused<4, 1><<<n, 256>>>(bufA, b0, bufB);

    // ---- Layer 1: 256 -> (4,64) ----
    sgemm<<<dim3(4, gy), 256>>>(bufB, W1, bufA, n, 256, 256, a1s, a1d, 4);
    aggregate_fused<4, 1><<<n, 256>>>(bufA, b1, bufB);

    // ---- Layer 2: 256 -> (1,64) ----
    sgemm<<<dim3(1, gy), 256>>>(bufB, W2, bufA, n, 256, 64, a2s, a2d, 1);
    aggregate_fused<1, 0><<<n, 64>>>(bufA, b2, bufB);

    // ---- Mean pool + head ----
    fill_f32<<<1, 64>>>(pool, 0.0f, 64);
    pool_kernel<<<128, 64>>>(bufB, n);
    head_kernel<<<1, 64>>>(hw, hb, out, n);
}

// round 8
// speedup vs baseline: 1.8004x; 1.2721x over previous
#include <cuda_runtime.h>
#include <math.h>
#include <stdint.h>

// ---------------------------------------------------------------------------
// GAT_23888608101379: 3-layer GAT + mean pool + linear head.
//   - CSR build (histogram, parallel 2-level scan, scatter)
//   - per layer: TF32 tensor-core GEMM (128x64 tile, fused alpha epilogue)
//                -> fused softmax+aggregate (CSR, no atomics)
//   - mean pool -> 64x64 head
// ---------------------------------------------------------------------------

#define MAXN 50000
#define MAXE 800000
#define MAXET (MAXE + MAXN)
#define NB_MAX 64

__device__ int   g_is64;
__device__ float g_bufA[MAXN * 256];   // GEMM output h
__device__ float g_bufB[MAXN * 256];   // layer output / next input
__device__ float g_as[MAXN * 4];
__device__ float g_ad[MAXN * 4];
__device__ int   g_rowptr[MAXN + 1];
__device__ int   g_cursor[MAXN];
__device__ int   g_csr_src[MAXET];
__device__ int   g_aux[NB_MAX];
__device__ float g_pool[64];

// ---------------------------------------------------------------------------

__global__ void detect_kernel(const void* ei, int n) {
    if (blockIdx.x == 0 && threadIdx.x == 0) {
        const long long* p = (const long long*)ei;
        int ok = 1;
        for (int i = 0; i < 64; i++) {
            long long v = p[i];
            if (v < 0 || v >= (long long)n) { ok = 0; break; }
        }
        g_is64 = ok;
    }
}

__device__ __forceinline__ void get_edge(const void* ei, int is64, int E, int e,
                                         int& src, int& dst) {
    if (e < E) {
        if (is64) {
            const long long* p = (const long long*)ei;
            src = (int)p[e];
            dst = (int)p[E + e];
        } else {
            const int* p = (const int*)ei;
            src = p[e];
            dst = p[E + e];
        }
    } else {            // self loop
        src = e - E;
        dst = src;
    }
}

__global__ void fill_i32(int* p, int v, int n) {
    int i = blockIdx.x * blockDim.x + threadIdx.x;
    if (i < n) p[i] = v;
}

__global__ void fill_f32(float* p, float v, int n) {
    int i = blockIdx.x * blockDim.x + threadIdx.x;
    if (i < n) p[i] = v;
}

__global__ void hist_kernel(const void* ei, int E, int n) {
    int is64 = g_is64;
    int et = E + n;
    for (int e = blockIdx.x * blockDim.x + threadIdx.x; e < et;
         e += gridDim.x * blockDim.x) {
        int src, dst;
        get_edge(ei, is64, E, e, src, dst);
        atomicAdd(&g_cursor[dst], 1);
    }
}

// ---- 2-level parallel exclusive scan of counts -> rowptr ----
__global__ void scan_local(int n) {           // grid = nb, block = 1024
    __shared__ int sh[1024];
    int b = blockIdx.x, tid = threadIdx.x;
    int i = b * 1024 + tid;
    int v = (i < n) ? g_cursor[i] : 0;
    sh[tid] = v;
    __syncthreads();
    for (int off = 1; off < 1024; off <<= 1) {
        int t = (tid >= off) ? sh[tid - off] : 0;
        __syncthreads();
        sh[tid] += t;
        __syncthreads();
    }
    if (i < n) g_rowptr[i + 1] = sh[tid];
    if (tid == 1023) g_aux[b] = sh[1023];
}

__global__ void scan_aux(int nb) {            // 1 thread, nb <= 64
    if (threadIdx.x == 0) {
        int s = 0;
        for (int b = 0; b < nb; b++) { int v = g_aux[b]; g_aux[b] = s; s += v; }
        g_rowptr[0] = 0;
    }
}

__global__ void scan_add(int n) {             // grid = nb, block = 1024
    int b = blockIdx.x;
    int i = b * 1024 + threadIdx.x;
    if (i < n) g_rowptr[i + 1] += g_aux[b];
}

__global__ void copy_cursor(int n) {
    int i = blockIdx.x * blockDim.x + threadIdx.x;
    if (i < n) g_cursor[i] = g_rowptr[i];
}

__global__ void scatter_kernel(const void* ei, int E, int n) {
    int is64 = g_is64;
    int et = E + n;
    for (int e = blockIdx.x * blockDim.x + threadIdx.x; e < et;
         e += gridDim.x * blockDim.x) {
        int src, dst;
        get_edge(ei, is64, E, e, src, dst);
        int pos = atomicAdd(&g_cursor[dst], 1);
        g_csr_src[pos] = src;
    }
}

// ---------------------------------------------------------------------------
// TF32 tensor-core GEMM: C[n,M] = A[n,K] @ B[K,M].
// BM=128, BN=64, BK=16, 256 threads = 8 warps (4 x 2), warp tile 32x32,
// mma.sync.m16n8k8.tf32 (2 M-frags x 4 N-frags per warp per k-step).
// SMEM: A [128][20] (padded, conflict-free), B [16][72], pre-converted tf32.
// Register prefetch of next tile; single smem buffer.
// The 64-col block tile == one head -> alpha_s/alpha_d computed in epilogue
// from fragments (quad shuffles + smem atomics).
// ---------------------------------------------------------------------------

__device__ __forceinline__ uint32_t f2tf(float f) {
    uint32_t u;
    asm("cvt.rna.tf32.f32 %0, %1;" : "=r"(u) : "f"(f));
    return u;
}

__device__ __forceinline__ void st4_tf(uint32_t* p, float4 v) {
    uint4 u;
    u.x = f2tf(v.x); u.y = f2tf(v.y); u.z = f2tf(v.z); u.w = f2tf(v.w);
    *(uint4*)p = u;
}

__device__ __forceinline__ void mma_tf32(float* d, const uint32_t* a,
                                         const uint32_t* b) {
    asm volatile(
        "mma.sync.aligned.m16n8k8.row.col.f32.tf32.tf32.f32 "
        "{%0,%1,%2,%3}, {%4,%5,%6,%7}, {%8,%9}, {%0,%1,%2,%3};\n"
        : "+f"(d[0]), "+f"(d[1]), "+f"(d[2]), "+f"(d[3])
        : "r"(a[0]), "r"(a[1]), "r"(a[2]), "r"(a[3]), "r"(b[0]), "r"(b[1]));
}

__global__ __launch_bounds__(256)
void sgemm_tc(const float* __restrict__ A, const float* __restrict__ B,
              float* __restrict__ C, int n, int K, int M,
              const float* __restrict__ avs, const float* __restrict__ avd,
              int H) {
    __shared__ uint32_t As[128][20];   // [row][k], pitch 20 (conflict-free)
    __shared__ uint32_t Bs[16][72];    // [k][col], pitch 72 (conflict-free)
    __shared__ float ps_sm[128], pd_sm[128];

    int tid = threadIdx.x;
    int lane = tid & 31, wid = tid >> 5;
    int wm = wid >> 1, wn = wid & 1;
    int rowBase = blockIdx.y * 128;
    int colBase = blockIdx.x * 64;
    int head = blockIdx.x;
    int qr = lane >> 2, qc = lane & 3;      // quad row / quad col

    // loader indices
    int ar = tid >> 1;                  // 0..127 (A row)
    int aq = (tid & 1) * 8;             // A col offset: 0 or 8
    int br = tid >> 4;                  // 0..15   (B k-row)
    int bc = (tid & 15) * 4;            // 0..60   (B col)

    if (tid < 128) { ps_sm[tid] = 0.0f; pd_sm[tid] = 0.0f; }

    // ---- load tile 0 ----
    {
        float4 a0v = make_float4(0, 0, 0, 0), a1v = a0v;
        if (rowBase + ar < n) {
            a0v = *(const float4*)&A[(size_t)(rowBase + ar) * K + aq];
            a1v = *(const float4*)&A[(size_t)(rowBase + ar) * K + aq + 4];
        }
        float4 bv = *(const float4*)&B[(size_t)br * M + colBase + bc];
        st4_tf(&As[ar][aq], a0v);
        st4_tf(&As[ar][aq + 4], a1v);
        st4_tf(&Bs[br][bc], bv);
    }
    __syncthreads();

    float acc[2][4][4];
#pragma unroll
    for (int mt = 0; mt < 2; mt++)
#pragma unroll
        for (int nt = 0; nt < 4; nt++)
#pragma unroll
            for (int j = 0; j < 4; j++) acc[mt][nt][j] = 0.0f;

    int nk = K >> 4;
    for (int t = 0; t < nk; t++) {
        float4 aP0, aP1, bP;
        bool has = (t + 1 < nk);
        if (has) {
            int k0 = (t + 1) << 4;
            aP0 = make_float4(0, 0, 0, 0); aP1 = aP0;
            if (rowBase + ar < n) {
                aP0 = *(const float4*)&A[(size_t)(rowBase + ar) * K + k0 + aq];
                aP1 = *(const float4*)&A[(size_t)(rowBase + ar) * K + k0 + aq + 4];
            }
            bP = *(const float4*)&B[(size_t)(k0 + br) * M + colBase + bc];
        }
#pragma unroll
        for (int ks = 0; ks < 2; ks++) {
            int kk = ks * 8;
            uint32_t af[2][4];
#pragma unroll
            for (int mt = 0; mt < 2; mt++) {
                int r0 = wm * 32 + mt * 16 + qr;
                int c0 = kk + qc;
                af[mt][0] = As[r0][c0];
                af[mt][1] = As[r0 + 8][c0];
                af[mt][2] = As[r0][c0 + 4];
                af[mt][3] = As[r0 + 8][c0 + 4];
            }
            uint32_t bf[4][2];
#pragma unroll
            for (int nt = 0; nt < 4; nt++) {
                int c = wn * 32 + nt * 8 + qr;
                int r = kk + qc;
                bf[nt][0] = Bs[r][c];
                bf[nt][1] = Bs[r + 4][c];
            }
#pragma unroll
            for (int mt = 0; mt < 2; mt++)
#pragma unroll
                for (int nt = 0; nt < 4; nt++)
                    mma_tf32(acc[mt][nt], af[mt], bf[nt]);
        }
        if (has) {
            __syncthreads();
            st4_tf(&As[ar][aq], aP0);
            st4_tf(&As[ar][aq + 4], aP1);
            st4_tf(&Bs[br][bc], bP);
            __syncthreads();
        }
    }

    // ---- store C tile (float2 per fragment row-pair) ----
#pragma unroll
    for (int mt = 0; mt < 2; mt++) {
#pragma unroll
        for (int nt = 0; nt < 4; nt++) {
            int r = rowBase + wm * 32 + mt * 16 + qr;
            int c = colBase + wn * 32 + nt * 8 + qc * 2;
            if (r < n) {
                float2 v0 = make_float2(acc[mt][nt][0], acc[mt][nt][1]);
                *(float2*)&C[(size_t)r * M + c] = v0;
            }
            if (r + 8 < n) {
                float2 v1 = make_float2(acc[mt][nt][2], acc[mt][nt][3]);
                *(float2*)&C[(size_t)(r + 8) * M + c] = v1;
            }
        }
    }

    // ---- fused alpha epilogue ----
    float av_s[8], av_d[8];
#pragma unroll
    for (int nt = 0; nt < 4; nt++)
#pragma unroll
        for (int j = 0; j < 2; j++) {
            int c = wn * 32 + nt * 8 + qc * 2 + j;
            av_s[nt * 2 + j] = __ldg(&avs[head * 64 + c]);
            av_d[nt * 2 + j] = __ldg(&avd[head * 64 + c]);
        }
#pragma unroll
    for (int mt = 0; mt < 2; mt++) {
#pragma unroll
        for (int half = 0; half < 2; half++) {
            float ps = 0.0f, pd = 0.0f;
#pragma unroll
            for (int nt = 0; nt < 4; nt++)
#pragma unroll
                for (int j = 0; j < 2; j++) {
                    float v = acc[mt][nt][half * 2 + j];
                    ps = fmaf(v, av_s[nt * 2 + j], ps);
                    pd = fmaf(v, av_d[nt * 2 + j], pd);
                }
            // reduce over the quad (lanes differing in qc only)
            ps += __shfl_xor_sync(0xffffffffu, ps, 1);
            ps += __shfl_xor_sync(0xffffffffu, ps, 2);
            pd += __shfl_xor_sync(0xffffffffu, pd, 1);
            pd += __shfl_xor_sync(0xffffffffu, pd, 2);
            if (qc == 0) {
                int rloc = wm * 32 + mt * 16 + qr + half * 8;
                atomicAdd(&ps_sm[rloc], ps);   // 2 N-warps accumulate
                atomicAdd(&pd_sm[rloc], pd);
            }
        }
    }
    __syncthreads();
    if (tid < 128) {
        int r = rowBase + tid;
        if (r < n) {
            g_as[r * H + head] = ps_sm[tid];
            g_ad[r * H + head] = pd_sm[tid];
        }
    }
}

// ---------------------------------------------------------------------------
// Fused softmax + aggregation over CSR row of dst.
// Block = H*64 threads per dst node.
// ---------------------------------------------------------------------------
template <int H, int RELU>
__global__ void aggregate_fused(const float* __restrict__ Hm,
                                const float* __restrict__ bias,
                                float* __restrict__ out) {
    const int M = H * 64;
    int dst = blockIdx.x;
    int t = threadIdx.x;
    int h = t >> 6;
    int lane = t & 31;
    int wid = t >> 5;
    int beg = g_rowptr[dst];
    int end = g_rowptr[dst + 1];

    __shared__ float sm_m[H];
    __shared__ float sm_inv[H];
    __shared__ int   sm_src[32];
    __shared__ float sm_w[32][H];

    float ad_h = 0.0f;
    if (wid < H) {
        ad_h = g_ad[dst * H + wid];
        float mx = -INFINITY;
        for (int j = beg + lane; j < end; j += 32) {
            float e = __ldg(&g_as[__ldg(&g_csr_src[j]) * H + wid]) + ad_h;
            e = (e > 0.0f) ? e : 0.2f * e;
            mx = fmaxf(mx, e);
        }
#pragma unroll
        for (int o = 16; o; o >>= 1)
            mx = fmaxf(mx, __shfl_xor_sync(0xffffffffu, mx, o));
        float s = 0.0f;
        for (int j = beg + lane; j < end; j += 32) {
            float e = __ldg(&g_as[__ldg(&g_csr_src[j]) * H + wid]) + ad_h;
            e = (e > 0.0f) ? e : 0.2f * e;
            s += expf(e - mx);
        }
#pragma unroll
        for (int o = 16; o; o >>= 1)
            s += __shfl_xor_sync(0xffffffffu, s, o);
        if (lane == 0) { sm_m[wid] = mx; sm_inv[wid] = 1.0f / (s + 1e-16f); }
    }
    __syncthreads();
    float m_h = 0.0f, inv_h = 0.0f;
    if (wid < H) { m_h = sm_m[wid]; inv_h = sm_inv[wid]; }

    float acc0 = 0.0f, acc1 = 0.0f;
    for (int c0 = beg; c0 < end; c0 += 32) {
        int cnt = min(32, end - c0);
        if (wid < H && lane < cnt) {
            int src = __ldg(&g_csr_src[c0 + lane]);
            if (wid == 0) sm_src[lane] = src;
            float e = __ldg(&g_as[src * H + wid]) + ad_h;
            e = (e > 0.0f) ? e : 0.2f * e;
            sm_w[lane][wid] = expf(e - m_h) * inv_h;
        }
        __syncthreads();
        int i = 0;
        for (; i + 1 < cnt; i += 2) {
            acc0 = fmaf(sm_w[i][h],     __ldg(&Hm[(size_t)sm_src[i] * M + t]),     acc0);
            acc1 = fmaf(sm_w[i + 1][h], __ldg(&Hm[(size_t)sm_src[i + 1] * M + t]), acc1);
        }
        if (i < cnt)
            acc0 = fmaf(sm_w[i][h], __ldg(&Hm[(size_t)sm_src[i] * M + t]), acc0);
        __syncthreads();
    }
    float o = acc0 + acc1 + bias[t];
    if (RELU) o = fmaxf(o, 0.0f);
    out[(size_t)dst * M + t] = o;
}

// ---------------------------------------------------------------------------

__global__ void pool_kernel(const float* __restrict__ X, int n) {
    int c = threadIdx.x;   // 64
    float s = 0.0f;
    for (int r = blockIdx.x; r < n; r += gridDim.x)
        s += X[(size_t)r * 64 + c];
    atomicAdd(&g_pool[c], s);
}

__global__ void head_kernel(const float* __restrict__ hw,
                            const float* __restrict__ hb,
                            float* __restrict__ out, int n) {
    int j = threadIdx.x;   // 64
    float inv = 1.0f / (float)n;
    float s = 0.0f;
#pragma unroll
    for (int c = 0; c < 64; c++)
        s = fmaf(g_pool[c] * inv, hw[c * 64 + j], s);
    out[j] = s + hb[j];
}

// ---------------------------------------------------------------------------

extern "C" void kernel_launch(void* const* d_in, const int* in_sizes, int n_in,
                              void* d_out, int out_size) {
    const float* x   = (const float*)d_in[0];
    const void*  ei  = d_in[1];
    const float* W0  = (const float*)d_in[2];
    const float* a0s = (const float*)d_in[3];
    const float* a0d = (const float*)d_in[4];
    const float* b0  = (const float*)d_in[5];
    const float* W1  = (const float*)d_in[6];
    const float* a1s = (const float*)d_in[7];
    const float* a1d = (const float*)d_in[8];
    const float* b1  = (const float*)d_in[9];
    const float* W2  = (const float*)d_in[10];
    const float* a2s = (const float*)d_in[11];
    const float* a2d = (const float*)d_in[12];
    const float* b2  = (const float*)d_in[13];
    const float* hw  = (const float*)d_in[14];
    const float* hb  = (const float*)d_in[15];
    float* out = (float*)d_out;

    int n = in_sizes[0] / 128;
    int E = in_sizes[1] / 2;
    int et = E + n;

    float *bufA, *bufB, *pool;
    int *gcursor;
    cudaGetSymbolAddress((void**)&bufA, g_bufA);
    cudaGetSymbolAddress((void**)&bufB, g_bufB);
    cudaGetSymbolAddress((void**)&pool, g_pool);
    cudaGetSymbolAddress((void**)&gcursor, g_cursor);

    int eblocks = (et + 255) / 256;
    if (eblocks > 4096) eblocks = 4096;
    int nb = (n + 1023) / 1024;

    // 0. dtype detection
    detect_kernel<<<1, 32>>>(ei, n);

    // 1. CSR build (dst-indexed)
    fill_i32<<<(n + 255) / 256, 256>>>(gcursor, 0, n);
    hist_kernel<<<eblocks, 256>>>(ei, E, n);
    scan_local<<<nb, 1024>>>(n);
    scan_aux<<<1, 32>>>(nb);
    scan_add<<<nb, 1024>>>(n);
    copy_cursor<<<(n + 255) / 256, 256>>>(n);
    scatter_kernel<<<eblocks, 256>>>(ei, E, n);

    int gy = (n + 127) / 128;

    // ---- Layer 0: 128 -> (4,64) ----
    sgemm_tc<<<dim3(4, gy), 256>>>(x, W0, bufA, n, 128, 256, a0s, a0d, 4);
    aggregate_fused<4, 1><<<n, 256>>>(bufA, b0, bufB);

    // ---- Layer 1: 256 -> (4,64) ----
    sgemm_tc<<<dim3(4, gy), 256>>>(bufB, W1, bufA, n, 256, 256, a1s, a1d, 4);
    aggregate_fused<4, 1><<<n, 256>>>(bufA, b1, bufB);

    // ---- Layer 2: 256 -> (1,64) ----
    sgemm_tc<<<dim3(1, gy), 256>>>(bufB, W2, bufA, n, 256, 64, a2s, a2d, 1);
    aggregate_fused<1, 0><<<n, 64>>>(bufA, b2, bufB);

    // ---- Mean pool + head ----
    fill_f32<<<1, 64>>>(pool, 0.0f, 64);
    pool_kernel<<<128, 64>>>(bufB, n);
    head_kernel<<<1, 64>>>(hw, hb, out, n);
}

// round 10
// speedup vs baseline: 2.5607x; 1.4223x over previous
#include <cuda_runtime.h>
#include <math.h>
#include <stdint.h>

// ---------------------------------------------------------------------------
// GAT_23888608101379: 3-layer GAT + mean pool + linear head.
//   - CSR build (histogram, parallel 2-level scan, scatter)
//   - per layer: TF32 tensor-core GEMM (128x64 tile, fused alpha epilogue)
//                -> sync-free fused softmax+aggregate (CSR, shuffles only)
//   - mean pool -> 64x64 head
// ---------------------------------------------------------------------------

#define MAXN 50000
#define MAXE 800000
#define MAXET (MAXE + MAXN)
#define NB_MAX 64
#define NEG_BIG (-1e30f)

__device__ int   g_is64;
__device__ float g_bufA[MAXN * 256];   // GEMM output h
__device__ float g_bufB[MAXN * 256];   // layer output / next input
__device__ float g_as[MAXN * 4];
__device__ float g_ad[MAXN * 4];
__device__ int   g_rowptr[MAXN + 1];
__device__ int   g_cursor[MAXN];
__device__ int   g_csr_src[MAXET];
__device__ int   g_aux[NB_MAX];
__device__ float g_pool[64];

// ---------------------------------------------------------------------------

__global__ void detect_kernel(const void* ei, int n) {
    if (blockIdx.x == 0 && threadIdx.x == 0) {
        const long long* p = (const long long*)ei;
        int ok = 1;
        for (int i = 0; i < 64; i++) {
            long long v = p[i];
            if (v < 0 || v >= (long long)n) { ok = 0; break; }
        }
        g_is64 = ok;
    }
}

__device__ __forceinline__ void get_edge(const void* ei, int is64, int E, int e,
                                         int& src, int& dst) {
    if (e < E) {
        if (is64) {
            const long long* p = (const long long*)ei;
            src = (int)p[e];
            dst = (int)p[E + e];
        } else {
            const int* p = (const int*)ei;
            src = p[e];
            dst = p[E + e];
        }
    } else {            // self loop
        src = e - E;
        dst = src;
    }
}

__global__ void fill_i32(int* p, int v, int n) {
    int i = blockIdx.x * blockDim.x + threadIdx.x;
    if (i < n) p[i] = v;
}

__global__ void fill_f32(float* p, float v, int n) {
    int i = blockIdx.x * blockDim.x + threadIdx.x;
    if (i < n) p[i] = v;
}

__global__ void hist_kernel(const void* ei, int E, int n) {
    int is64 = g_is64;
    int et = E + n;
    for (int e = blockIdx.x * blockDim.x + threadIdx.x; e < et;
         e += gridDim.x * blockDim.x) {
        int src, dst;
        get_edge(ei, is64, E, e, src, dst);
        atomicAdd(&g_cursor[dst], 1);
    }
}

// ---- 2-level parallel exclusive scan of counts -> rowptr ----
__global__ void scan_local(int n) {           // grid = nb, block = 1024
    __shared__ int sh[1024];
    int b = blockIdx.x, tid = threadIdx.x;
    int i = b * 1024 + tid;
    int v = (i < n) ? g_cursor[i] : 0;
    sh[tid] = v;
    __syncthreads();
    for (int off = 1; off < 1024; off <<= 1) {
        int t = (tid >= off) ? sh[tid - off] : 0;
        __syncthreads();
        sh[tid] += t;
        __syncthreads();
    }
    if (i < n) g_rowptr[i + 1] = sh[tid];
    if (tid == 1023) g_aux[b] = sh[1023];
}

__global__ void scan_aux(int nb) {            // 1 thread, nb <= 64
    if (threadIdx.x == 0) {
        int s = 0;
        for (int b = 0; b < nb; b++) { int v = g_aux[b]; g_aux[b] = s; s += v; }
        g_rowptr[0] = 0;
    }
}

__global__ void scan_add(int n) {             // grid = nb, block = 1024
    int b = blockIdx.x;
    int i = b * 1024 + threadIdx.x;
    if (i < n) g_rowptr[i + 1] += g_aux[b];
}

__global__ void copy_cursor(int n) {
    int i = blockIdx.x * blockDim.x + threadIdx.x;
    if (i < n) g_cursor[i] = g_rowptr[i];
}

__global__ void scatter_kernel(const void* ei, int E, int n) {
    int is64 = g_is64;
    int et = E + n;
    for (int e = blockIdx.x * blockDim.x + threadIdx.x; e < et;
         e += gridDim.x * blockDim.x) {
        int src, dst;
        get_edge(ei, is64, E, e, src, dst);
        int pos = atomicAdd(&g_cursor[dst], 1);
        g_csr_src[pos] = src;
    }
}

// ---------------------------------------------------------------------------
// TF32 tensor-core GEMM: C[n,M] = A[n,K] @ B[K,M].
// BM=128, BN=64, BK=16, 256 threads = 8 warps (4 x 2), warp tile 32x32,
// mma.sync.m16n8k8.tf32. Fused alpha epilogue.
// ---------------------------------------------------------------------------

__device__ __forceinline__ uint32_t f2tf(float f) {
    uint32_t u;
    asm("cvt.rna.tf32.f32 %0, %1;" : "=r"(u) : "f"(f));
    return u;
}

__device__ __forceinline__ void st4_tf(uint32_t* p, float4 v) {
    uint4 u;
    u.x = f2tf(v.x); u.y = f2tf(v.y); u.z = f2tf(v.z); u.w = f2tf(v.w);
    *(uint4*)p = u;
}

__device__ __forceinline__ void mma_tf32(float* d, const uint32_t* a,
                                         const uint32_t* b) {
    asm volatile(
        "mma.sync.aligned.m16n8k8.row.col.f32.tf32.tf32.f32 "
        "{%0,%1,%2,%3}, {%4,%5,%6,%7}, {%8,%9}, {%0,%1,%2,%3};\n"
        : "+f"(d[0]), "+f"(d[1]), "+f"(d[2]), "+f"(d[3])
        : "r"(a[0]), "r"(a[1]), "r"(a[2]), "r"(a[3]), "r"(b[0]), "r"(b[1]));
}

__global__ __launch_bounds__(256)
void sgemm_tc(const float* __restrict__ A, const float* __restrict__ B,
              float* __restrict__ C, int n, int K, int M,
              const float* __restrict__ avs, const float* __restrict__ avd,
              int H) {
    __shared__ uint32_t As[128][20];   // [row][k], pitch 20 (conflict-free)
    __shared__ uint32_t Bs[16][72];    // [k][col], pitch 72 (conflict-free)
    __shared__ float ps_sm[128], pd_sm[128];

    int tid = threadIdx.x;
    int lane = tid & 31, wid = tid >> 5;
    int wm = wid >> 1, wn = wid & 1;
    int rowBase = blockIdx.y * 128;
    int colBase = blockIdx.x * 64;
    int head = blockIdx.x;
    int qr = lane >> 2, qc = lane & 3;      // quad row / quad col

    // loader indices
    int ar = tid >> 1;                  // 0..127 (A row)
    int aq = (tid & 1) * 8;             // A col offset: 0 or 8
    int br = tid >> 4;                  // 0..15   (B k-row)
    int bc = (tid & 15) * 4;            // 0..60   (B col)

    if (tid < 128) { ps_sm[tid] = 0.0f; pd_sm[tid] = 0.0f; }

    // ---- load tile 0 ----
    {
        float4 a0v = make_float4(0, 0, 0, 0), a1v = a0v;
        if (rowBase + ar < n) {
            a0v = *(const float4*)&A[(size_t)(rowBase + ar) * K + aq];
            a1v = *(const float4*)&A[(size_t)(rowBase + ar) * K + aq + 4];
        }
        float4 bv = *(const float4*)&B[(size_t)br * M + colBase + bc];
        st4_tf(&As[ar][aq], a0v);
        st4_tf(&As[ar][aq + 4], a1v);
        st4_tf(&Bs[br][bc], bv);
    }
    __syncthreads();

    float acc[2][4][4];
#pragma unroll
    for (int mt = 0; mt < 2; mt++)
#pragma unroll
        for (int nt = 0; nt < 4; nt++)
#pragma unroll
            for (int j = 0; j < 4; j++) acc[mt][nt][j] = 0.0f;

    int nk = K >> 4;
    for (int t = 0; t < nk; t++) {
        float4 aP0, aP1, bP;
        bool has = (t + 1 < nk);
        if (has) {
            int k0 = (t + 1) << 4;
            aP0 = make_float4(0, 0, 0, 0); aP1 = aP0;
            if (rowBase + ar < n) {
                aP0 = *(const float4*)&A[(size_t)(rowBase + ar) * K + k0 + aq];
                aP1 = *(const float4*)&A[(size_t)(rowBase + ar) * K + k0 + aq + 4];
            }
            bP = *(const float4*)&B[(size_t)(k0 + br) * M + colBase + bc];
        }
#pragma unroll
        for (int ks = 0; ks < 2; ks++) {
            int kk = ks * 8;
            uint32_t af[2][4];
#pragma unroll
            for (int mt = 0; mt < 2; mt++) {
                int r0 = wm * 32 + mt * 16 + qr;
                int c0 = kk + qc;
                af[mt][0] = As[r0][c0];
                af[mt][1] = As[r0 + 8][c0];
                af[mt][2] = As[r0][c0 + 4];
                af[mt][3] = As[r0 + 8][c0 + 4];
            }
            uint32_t bf[4][2];
#pragma unroll
            for (int nt = 0; nt < 4; nt++) {
                int c = wn * 32 + nt * 8 + qr;
                int r = kk + qc;
                bf[nt][0] = Bs[r][c];
                bf[nt][1] = Bs[r + 4][c];
            }
#pragma unroll
            for (int mt = 0; mt < 2; mt++)
#pragma unroll
                for (int nt = 0; nt < 4; nt++)
                    mma_tf32(acc[mt][nt], af[mt], bf[nt]);
        }
        if (has) {
            __syncthreads();
            st4_tf(&As[ar][aq], aP0);
            st4_tf(&As[ar][aq + 4], aP1);
            st4_tf(&Bs[br][bc], bP);
            __syncthreads();
        }
    }

    // ---- store C tile ----
#pragma unroll
    for (int mt = 0; mt < 2; mt++) {
#pragma unroll
        for (int nt = 0; nt < 4; nt++) {
            int r = rowBase + wm * 32 + mt * 16 + qr;
            int c = colBase + wn * 32 + nt * 8 + qc * 2;
            if (r < n) {
                float2 v0 = make_float2(acc[mt][nt][0], acc[mt][nt][1]);
                *(float2*)&C[(size_t)r * M + c] = v0;
            }
            if (r + 8 < n) {
                float2 v1 = make_float2(acc[mt][nt][2], acc[mt][nt][3]);
                *(float2*)&C[(size_t)(r + 8) * M + c] = v1;
            }
        }
    }

    // ---- fused alpha epilogue ----
    float av_s[8], av_d[8];
#pragma unroll
    for (int nt = 0; nt < 4; nt++)
#pragma unroll
        for (int j = 0; j < 2; j++) {
            int c = wn * 32 + nt * 8 + qc * 2 + j;
            av_s[nt * 2 + j] = __ldg(&avs[head * 64 + c]);
            av_d[nt * 2 + j] = __ldg(&avd[head * 64 + c]);
        }
#pragma unroll
    for (int mt = 0; mt < 2; mt++) {
#pragma unroll
        for (int half = 0; half < 2; half++) {
            float ps = 0.0f, pd = 0.0f;
#pragma unroll
            for (int nt = 0; nt < 4; nt++)
#pragma unroll
                for (int j = 0; j < 2; j++) {
                    float v = acc[mt][nt][half * 2 + j];
                    ps = fmaf(v, av_s[nt * 2 + j], ps);
                    pd = fmaf(v, av_d[nt * 2 + j], pd);
                }
            ps += __shfl_xor_sync(0xffffffffu, ps, 1);
            ps += __shfl_xor_sync(0xffffffffu, ps, 2);
            pd += __shfl_xor_sync(0xffffffffu, pd, 1);
            pd += __shfl_xor_sync(0xffffffffu, pd, 2);
            if (qc == 0) {
                int rloc = wm * 32 + mt * 16 + qr + half * 8;
                atomicAdd(&ps_sm[rloc], ps);
                atomicAdd(&pd_sm[rloc], pd);
            }
        }
    }
    __syncthreads();
    if (tid < 128) {
        int r = rowBase + tid;
        if (r < n) {
            g_as[r * H + head] = ps_sm[tid];
            g_ad[r * H + head] = pd_sm[tid];
        }
    }
}

// ---------------------------------------------------------------------------
// Sync-free fused softmax + aggregation, H=4 (M=256).
// 128 threads = 2 dst nodes; 64 threads per dst (thread owns 4 channels).
// Thread's softmax head (lt>>4) == its gather head -> all stats in registers.
// Online softmax uses m init = NEG_BIG (finite!) so merging two empty lanes
// never produces (-inf) - (-inf) = NaN in expf.
// ---------------------------------------------------------------------------
__global__ __launch_bounds__(128)
void aggregate4(const float* __restrict__ Hm, const float* __restrict__ bias,
                float* __restrict__ out, int n) {
    int t = threadIdx.x;
    int lane = t & 31;
    int lt = t & 63;
    int sub = t >> 6;
    int gh = lt >> 4;                  // head: equals warp*2 + (lane>>4)
    int dst = blockIdx.x * 2 + sub;
    if (dst >= n) return;

    int beg = g_rowptr[dst];
    int end = g_rowptr[dst + 1];
    float ad_h = g_ad[dst * 4 + gh];

    // ---- Phase A: online softmax stats over the row (16 lanes per head) ----
    float m = NEG_BIG, s = 0.0f;
    for (int j = beg + (lane & 15); j < end; j += 16) {
        int src = __ldg(&g_csr_src[j]);
        float e = __ldg(&g_as[src * 4 + gh]) + ad_h;
        e = (e > 0.0f) ? e : 0.2f * e;
        float nm = fmaxf(m, e);
        s = s * __expf(m - nm) + __expf(e - nm);
        m = nm;
    }
#pragma unroll
    for (int o = 8; o; o >>= 1) {
        float om = __shfl_xor_sync(0xffffffffu, m, o);
        float os = __shfl_xor_sync(0xffffffffu, s, o);
        float nm = fmaxf(m, om);
        s = s * __expf(m - nm) + os * __expf(om - nm);
        m = nm;
    }
    float inv = 1.0f / (s + 1e-16f);

    // ---- Phase B: weighted gather, 16-edge chunks ----
    float4 acc = make_float4(0, 0, 0, 0);
    int base = lane & 16;
    for (int c0 = beg; c0 < end; c0 += 16) {
        int cnt = min(16, end - c0);
        int i16 = lane & 15;
        int src = 0; float wv = 0.0f;
        if (i16 < cnt) {
            src = __ldg(&g_csr_src[c0 + i16]);
            float e = __ldg(&g_as[src * 4 + gh]) + ad_h;
            e = (e > 0.0f) ? e : 0.2f * e;
            wv = __expf(e - m) * inv;
        }
        for (int i = 0; i < cnt; i++) {
            int si = __shfl_sync(0xffffffffu, src, base + i);
            float wi = __shfl_sync(0xffffffffu, wv, base + i);
            float4 hv = *(const float4*)&Hm[(size_t)si * 256 + lt * 4];
            acc.x = fmaf(wi, hv.x, acc.x);
            acc.y = fmaf(wi, hv.y, acc.y);
            acc.z = fmaf(wi, hv.z, acc.z);
            acc.w = fmaf(wi, hv.w, acc.w);
        }
    }
    float4 bv = *(const float4*)&bias[lt * 4];
    acc.x = fmaxf(acc.x + bv.x, 0.0f);
    acc.y = fmaxf(acc.y + bv.y, 0.0f);
    acc.z = fmaxf(acc.z + bv.z, 0.0f);
    acc.w = fmaxf(acc.w + bv.w, 0.0f);
    *(float4*)&out[(size_t)dst * 256 + lt * 4] = acc;
}

// ---------------------------------------------------------------------------
// Sync-free fused softmax + aggregation, H=1 (M=64). One warp per dst,
// 4 dst per 128-thread block; lane owns 2 channels (float2). No ReLU.
// ---------------------------------------------------------------------------
__global__ __launch_bounds__(128)
void aggregate1(const float* __restrict__ Hm, const float* __restrict__ bias,
                float* __restrict__ out, int n) {
    int t = threadIdx.x;
    int lane = t & 31;
    int wid = t >> 5;
    int dst = blockIdx.x * 4 + wid;
    if (dst >= n) return;

    int beg = g_rowptr[dst];
    int end = g_rowptr[dst + 1];
    float ad_h = g_ad[dst];

    float m = NEG_BIG, s = 0.0f;
    for (int j = beg + lane; j < end; j += 32) {
        int src = __ldg(&g_csr_src[j]);
        float e = __ldg(&g_as[src]) + ad_h;
        e = (e > 0.0f) ? e : 0.2f * e;
        float nm = fmaxf(m, e);
        s = s * __expf(m - nm) + __expf(e - nm);
        m = nm;
    }
#pragma unroll
    for (int o = 16; o; o >>= 1) {
        float om = __shfl_xor_sync(0xffffffffu, m, o);
        float os = __shfl_xor_sync(0xffffffffu, s, o);
        float nm = fmaxf(m, om);
        s = s * __expf(m - nm) + os * __expf(om - nm);
        m = nm;
    }
    float inv = 1.0f / (s + 1e-16f);

    float2 acc = make_float2(0, 0);
    for (int c0 = beg; c0 < end; c0 += 32) {
        int cnt = min(32, end - c0);
        int src = 0; float wv = 0.0f;
        if (lane < cnt) {
            src = __ldg(&g_csr_src[c0 + lane]);
            float e = __ldg(&g_as[src]) + ad_h;
            e = (e > 0.0f) ? e : 0.2f * e;
            wv = __expf(e - m) * inv;
        }
        for (int i = 0; i < cnt; i++) {
            int si = __shfl_sync(0xffffffffu, src, i);
            float wi = __shfl_sync(0xffffffffu, wv, i);
            float2 hv = *(const float2*)&Hm[(size_t)si * 64 + lane * 2];
            acc.x = fmaf(wi, hv.x, acc.x);
            acc.y = fmaf(wi, hv.y, acc.y);
        }
    }
    float2 bv = *(const float2*)&bias[lane * 2];
    acc.x += bv.x;
    acc.y += bv.y;
    *(float2*)&out[(size_t)dst * 64 + lane * 2] = acc;
}

// ---------------------------------------------------------------------------

__global__ void pool_kernel(const float* __restrict__ X, int n) {
    int c = threadIdx.x;   // 64
    float s = 0.0f;
    for (int r = blockIdx.x; r < n; r += gridDim.x)
        s += X[(size_t)r * 64 + c];
    atomicAdd(&g_pool[c], s);
}

__global__ void head_kernel(const float* __restrict__ hw,
                            const float* __restrict__ hb,
                            float* __restrict__ out, int n) {
    int j = threadIdx.x;   // 64
    float inv = 1.0f / (float)n;
    float s = 0.0f;
#pragma unroll
    for (int c = 0; c < 64; c++)
        s = fmaf(g_pool[c] * inv, hw[c * 64 + j], s);
    out[j] = s + hb[j];
}

// ---------------------------------------------------------------------------

extern "C" void kernel_launch(void* const* d_in, const int* in_sizes, int n_in,
                              void* d_out, int out_size) {
    const float* x   = (const float*)d_in[0];
    const void*  ei  = d_in[1];
    const float* W0  = (const float*)d_in[2];
    const float* a0s = (const float*)d_in[3];
    const float* a0d = (const float*)d_in[4];
    const float* b0  = (const float*)d_in[5];
    const float* W1  = (const float*)d_in[6];
    const float* a1s = (const float*)d_in[7];
    const float* a1d = (const float*)d_in[8];
    const float* b1  = (const float*)d_in[9];
    const float* W2  = (const float*)d_in[10];
    const float* a2s = (const float*)d_in[11];
    const float* a2d = (const float*)d_in[12];
    const float* b2  = (const float*)d_in[13];
    const float* hw  = (const float*)d_in[14];
    const float* hb  = (const float*)d_in[15];
    float* out = (float*)d_out;

    int n = in_sizes[0] / 128;
    int E = in_sizes[1] / 2;
    int et = E + n;

    float *bufA, *bufB, *pool;
    int *gcursor;
    cudaGetSymbolAddress((void**)&bufA, g_bufA);
    cudaGetSymbolAddress((void**)&bufB, g_bufB);
    cudaGetSymbolAddress((void**)&pool, g_pool);
    cudaGetSymbolAddress((void**)&gcursor, g_cursor);

    int eblocks = (et + 255) / 256;
    if (eblocks > 4096) eblocks = 4096;
    int nb = (n + 1023) / 1024;

    // 0. dtype detection
    detect_kernel<<<1, 32>>>(ei, n);

    // 1. CSR build (dst-indexed)
    fill_i32<<<(n + 255) / 256, 256>>>(gcursor, 0, n);
    hist_kernel<<<eblocks, 256>>>(ei, E, n);
    scan_local<<<nb, 1024>>>(n);
    scan_aux<<<1, 32>>>(nb);
    scan_add<<<nb, 1024>>>(n);
    copy_cursor<<<(n + 255) / 256, 256>>>(n);
    scatter_kernel<<<eblocks, 256>>>(ei, E, n);

    int gy = (n + 127) / 128;
    int ga4 = (n + 1) / 2;
    int ga1 = (n + 3) / 4;

    // ---- Layer 0: 128 -> (4,64) ----
    sgemm_tc<<<dim3(4, gy), 256>>>(x, W0, bufA, n, 128, 256, a0s, a0d, 4);
    aggregate4<<<ga4, 128>>>(bufA, b0, bufB, n);

    // ---- Layer 1: 256 -> (4,64) ----
    sgemm_tc<<<dim3(4, gy), 256>>>(bufB, W1, bufA, n, 256, 256, a1s, a1d, 4);
    aggregate4<<<ga4, 128>>>(bufA, b1, bufB, n);

    // ---- Layer 2: 256 -> (1,64) ----
    sgemm_tc<<<dim3(1, gy), 256>>>(bufB, W2, bufA, n, 256, 64, a2s, a2d, 1);
    aggregate1<<<ga1, 128>>>(bufA, b2, bufB, n);

    // ---- Mean pool + head ----
    fill_f32<<<1, 64>>>(pool, 0.0f, 64);
    pool_kernel<<<128, 64>>>(bufB, n);
    head_kernel<<<1, 64>>>(hw, hb, out, n);
}

// round 12
// speedup vs baseline: 2.6585x; 1.0382x over previous
#include <cuda_runtime.h>
#include <math.h>
#include <stdint.h>

// ---------------------------------------------------------------------------
// GAT_23888608101379: 3-layer GAT + mean pool + linear head.
//   - CSR build (histogram fused into GEMM-0, parallel 2-level scan, scatter)
//   - per layer: TF32 tensor-core GEMM (128x64 tile, double-buffered smem,
//                fused alpha epilogue) -> sync-free fused softmax+aggregate
//   - mean pool -> 64x64 head
// ---------------------------------------------------------------------------

#define MAXN 50000
#define MAXE 800000
#define MAXET (MAXE + MAXN)
#define NB_MAX 64
#define NEG_BIG (-1e30f)

__device__ int   g_is64;
__device__ float g_bufA[MAXN * 256];   // GEMM output h
__device__ float g_bufB[MAXN * 256];   // layer output / next input
__device__ float g_as[MAXN * 4];
__device__ float g_ad[MAXN * 4];
__device__ int   g_rowptr[MAXN + 1];
__device__ int   g_cursor[MAXN];
__device__ int   g_csr_src[MAXET];
__device__ int   g_aux[NB_MAX];
__device__ float g_pool[64];

// ---------------------------------------------------------------------------

__global__ void detect_kernel(const void* ei, int n) {
    // also zeroes the pool accumulator (written much later by pool_kernel)
    if (threadIdx.x < 64) g_pool[threadIdx.x] = 0.0f;
    if (threadIdx.x == 0) {
        const long long* p = (const long long*)ei;
        int ok = 1;
        for (int i = 0; i < 64; i++) {
            long long v = p[i];
            if (v < 0 || v >= (long long)n) { ok = 0; break; }
        }
        g_is64 = ok;
    }
}

__device__ __forceinline__ void get_edge(const void* ei, int is64, int E, int e,
                                         int& src, int& dst) {
    if (e < E) {
        if (is64) {
            const long long* p = (const long long*)ei;
            src = (int)p[e];
            dst = (int)p[E + e];
        } else {
            const int* p = (const int*)ei;
            src = p[e];
            dst = p[E + e];
        }
    } else {            // self loop
        src = e - E;
        dst = src;
    }
}

__global__ void fill_i32(int* p, int v, int n) {
    int i = blockIdx.x * blockDim.x + threadIdx.x;
    if (i < n) p[i] = v;
}

__device__ void hist_body(const void* ei, int E, int n, int b, int nbk) {
    int is64 = g_is64;
    int et = E + n;
    for (int e = b * 256 + threadIdx.x; e < et; e += nbk * 256) {
        int src, dst;
        get_edge(ei, is64, E, e, src, dst);
        atomicAdd(&g_cursor[dst], 1);
    }
}

// ---- 2-level parallel exclusive scan of counts -> rowptr (+cursor) ----
__global__ void scan_local(int n) {           // grid = nb, block = 1024
    __shared__ int sh[1024];
    int b = blockIdx.x, tid = threadIdx.x;
    int i = b * 1024 + tid;
    int v = (i < n) ? g_cursor[i] : 0;
    sh[tid] = v;
    __syncthreads();
    for (int off = 1; off < 1024; off <<= 1) {
        int t = (tid >= off) ? sh[tid - off] : 0;
        __syncthreads();
        sh[tid] += t;
        __syncthreads();
    }
    if (i < n) g_rowptr[i + 1] = sh[tid];
    if (tid == 1023) g_aux[b] = sh[1023];
}

__global__ void scan_aux(int nb) {            // 1 thread, nb <= 64
    if (threadIdx.x == 0) {
        int s = 0;
        for (int b = 0; b < nb; b++) { int v = g_aux[b]; g_aux[b] = s; s += v; }
        g_rowptr[0] = 0;
    }
}

__global__ void scan_add(int n) {             // grid = nb, block = 1024
    int b = blockIdx.x;
    int i = b * 1024 + threadIdx.x;
    if (i < n) {
        int cnt = g_cursor[i];                 // original per-dst count
        int v = g_rowptr[i + 1] + g_aux[b];    // final rowptr[i+1]
        g_rowptr[i + 1] = v;
        g_cursor[i] = v - cnt;                 // == final rowptr[i]
    }
}

__global__ void scatter_kernel(const void* ei, int E, int n) {
    int is64 = g_is64;
    int et = E + n;
    for (int e = blockIdx.x * blockDim.x + threadIdx.x; e < et;
         e += gridDim.x * blockDim.x) {
        int src, dst;
        get_edge(ei, is64, E, e, src, dst);
        int pos = atomicAdd(&g_cursor[dst], 1);
        g_csr_src[pos] = src;
    }
}

// ---------------------------------------------------------------------------
// TF32 tensor-core GEMM body: C[n,M] = A[n,K] @ B[K,M].
// BM=128, BN=64, BK=16, 256 threads = 8 warps (4 x 2), warp tile 32x32,
// mma.sync.m16n8k8.tf32, double-buffered smem (1 sync per k-tile).
// Fused alpha epilogue (the 64-col tile == one head).
// ---------------------------------------------------------------------------

__device__ __forceinline__ uint32_t f2tf(float f) {
    uint32_t u;
    asm("cvt.rna.tf32.f32 %0, %1;" : "=r"(u) : "f"(f));
    return u;
}

__device__ __forceinline__ void st4_tf(uint32_t* p, float4 v) {
    uint4 u;
    u.x = f2tf(v.x); u.y = f2tf(v.y); u.z = f2tf(v.z); u.w = f2tf(v.w);
    *(uint4*)p = u;
}

__device__ __forceinline__ void mma_tf32(float* d, const uint32_t* a,
                                         const uint32_t* b) {
    asm volatile(
        "mma.sync.aligned.m16n8k8.row.col.f32.tf32.tf32.f32 "
        "{%0,%1,%2,%3}, {%4,%5,%6,%7}, {%8,%9}, {%0,%1,%2,%3};\n"
        : "+f"(d[0]), "+f"(d[1]), "+f"(d[2]), "+f"(d[3])
        : "r"(a[0]), "r"(a[1]), "r"(a[2]), "r"(a[3]), "r"(b[0]), "r"(b[1]));
}

__device__ void sgemm_body(const float* __restrict__ A,
                           const float* __restrict__ B,
                           float* __restrict__ C, int n, int K, int M,
                           const float* __restrict__ avs,
                           const float* __restrict__ avd,
                           int H, int bx, int by) {
    __shared__ uint32_t As[2][128][20];  // [buf][row][k], pitch 20
    __shared__ uint32_t Bs[2][16][72];   // [buf][k][col], pitch 72
    __shared__ float ps_sm[128], pd_sm[128];

    int tid = threadIdx.x;
    int lane = tid & 31, wid = tid >> 5;
    int wm = wid >> 1, wn = wid & 1;
    int rowBase = by * 128;
    int colBase = bx * 64;
    int head = bx;
    int qr = lane >> 2, qc = lane & 3;

    int ar = tid >> 1;
    int aq = (tid & 1) * 8;
    int br = tid >> 4;
    int bc = (tid & 15) * 4;

    int tid128 = tid & 127;
    if (tid < 128) { ps_sm[tid] = 0.0f; pd_sm[tid] = 0.0f; }

    // ---- load tile 0 -> buf 0 ----
    {
        float4 a0v = make_float4(0, 0, 0, 0), a1v = a0v;
        if (rowBase + ar < n) {
            a0v = *(const float4*)&A[(size_t)(rowBase + ar) * K + aq];
            a1v = *(const float4*)&A[(size_t)(rowBase + ar) * K + aq + 4];
        }
        float4 bv = *(const float4*)&B[(size_t)br * M + colBase + bc];
        st4_tf(&As[0][ar][aq], a0v);
        st4_tf(&As[0][ar][aq + 4], a1v);
        st4_tf(&Bs[0][br][bc], bv);
    }
    __syncthreads();

    float acc[2][4][4];
#pragma unroll
    for (int mt = 0; mt < 2; mt++)
#pragma unroll
        for (int nt = 0; nt < 4; nt++)
#pragma unroll
            for (int j = 0; j < 4; j++) acc[mt][nt][j] = 0.0f;

    int nk = K >> 4;
    for (int t = 0; t < nk; t++) {
        int cur = t & 1, nxt = cur ^ 1;
        bool has = (t + 1 < nk);
        float4 aP0, aP1, bP;
        if (has) {
            int k0 = (t + 1) << 4;
            aP0 = make_float4(0, 0, 0, 0); aP1 = aP0;
            if (rowBase + ar < n) {
                aP0 = *(const float4*)&A[(size_t)(rowBase + ar) * K + k0 + aq];
                aP1 = *(const float4*)&A[(size_t)(rowBase + ar) * K + k0 + aq + 4];
            }
            bP = *(const float4*)&B[(size_t)(k0 + br) * M + colBase + bc];
        }
#pragma unroll
        for (int ks = 0; ks < 2; ks++) {
            int kk = ks * 8;
            uint32_t af[2][4];
#pragma unroll
            for (int mt = 0; mt < 2; mt++) {
                int r0 = wm * 32 + mt * 16 + qr;
                int c0 = kk + qc;
                af[mt][0] = As[cur][r0][c0];
                af[mt][1] = As[cur][r0 + 8][c0];
                af[mt][2] = As[cur][r0][c0 + 4];
                af[mt][3] = As[cur][r0 + 8][c0 + 4];
            }
            uint32_t bf[4][2];
#pragma unroll
            for (int nt = 0; nt < 4; nt++) {
                int c = wn * 32 + nt * 8 + qr;
                int r = kk + qc;
                bf[nt][0] = Bs[cur][r][c];
                bf[nt][1] = Bs[cur][r + 4][c];
            }
#pragma unroll
            for (int mt = 0; mt < 2; mt++)
#pragma unroll
                for (int nt = 0; nt < 4; nt++)
                    mma_tf32(acc[mt][nt], af[mt], bf[nt]);
        }
        if (has) {
            st4_tf(&As[nxt][ar][aq], aP0);
            st4_tf(&As[nxt][ar][aq + 4], aP1);
            st4_tf(&Bs[nxt][br][bc], bP);
            __syncthreads();
        }
    }

    // ---- store C tile ----
#pragma unroll
    for (int mt = 0; mt < 2; mt++) {
#pragma unroll
        for (int nt = 0; nt < 4; nt++) {
            int r = rowBase + wm * 32 + mt * 16 + qr;
            int c = colBase + wn * 32 + nt * 8 + qc * 2;
            if (r < n) {
                float2 v0 = make_float2(acc[mt][nt][0], acc[mt][nt][1]);
                *(float2*)&C[(size_t)r * M + c] = v0;
            }
            if (r + 8 < n) {
                float2 v1 = make_float2(acc[mt][nt][2], acc[mt][nt][3]);
                *(float2*)&C[(size_t)(r + 8) * M + c] = v1;
            }
        }
    }

    // ---- fused alpha epilogue ----
    float av_s[8], av_d[8];
#pragma unroll
    for (int nt = 0; nt < 4; nt++)
#pragma unroll
        for (int j = 0; j < 2; j++) {
            int c = wn * 32 + nt * 8 + qc * 2 + j;
            av_s[nt * 2 + j] = __ldg(&avs[head * 64 + c]);
            av_d[nt * 2 + j] = __ldg(&avd[head * 64 + c]);
        }
#pragma unroll
    for (int mt = 0; mt < 2; mt++) {
#pragma unroll
        for (int half = 0; half < 2; half++) {
            float ps = 0.0f, pd = 0.0f;
#pragma unroll
            for (int nt = 0; nt < 4; nt++)
#pragma unroll
                for (int j = 0; j < 2; j++) {
                    float v = acc[mt][nt][half * 2 + j];
                    ps = fmaf(v, av_s[nt * 2 + j], ps);
                    pd = fmaf(v, av_d[nt * 2 + j], pd);
                }
            ps += __shfl_xor_sync(0xffffffffu, ps, 1);
            ps += __shfl_xor_sync(0xffffffffu, ps, 2);
            pd += __shfl_xor_sync(0xffffffffu, pd, 1);
            pd += __shfl_xor_sync(0xffffffffu, pd, 2);
            if (qc == 0) {
                int rloc = wm * 32 + mt * 16 + qr + half * 8;
                atomicAdd(&ps_sm[rloc], ps);
                atomicAdd(&pd_sm[rloc], pd);
            }
        }
    }
    __syncthreads();
    if (tid < 128) {
        int r = rowBase + tid128;
        if (r < n) {
            g_as[r * H + head] = ps_sm[tid128];
            g_ad[r * H + head] = pd_sm[tid128];
        }
    }
}

__global__ __launch_bounds__(256)
void sgemm_tc(const float* __restrict__ A, const float* __restrict__ B,
              float* __restrict__ C, int n, int K, int M,
              const float* __restrict__ avs, const float* __restrict__ avd,
              int H) {
    sgemm_body(A, B, C, n, K, M, avs, avd, H, blockIdx.x, blockIdx.y);
}

// Fused: GEMM-0 (blocks [0, gemmBlocks)) + edge histogram (remaining blocks).
// Independent workloads: GEMM-0 reads x/W0; hist reads edge_index.
__global__ __launch_bounds__(256)
void gemm0_hist(const float* __restrict__ A, const float* __restrict__ B,
                float* __restrict__ C, int n,
                const float* __restrict__ avs, const float* __restrict__ avd,
                const void* ei, int E, int gemmBlocks) {
    int b = blockIdx.x;
    if (b < gemmBlocks) {
        sgemm_body(A, B, C, n, 128, 256, avs, avd, 4, b & 3, b >> 2);
    } else {
        hist_body(ei, E, n, b - gemmBlocks, gridDim.x - gemmBlocks);
    }
}

// ---------------------------------------------------------------------------
// Sync-free fused softmax + aggregation, H=4 (M=256).
// 128 threads = 2 dst nodes; 64 threads per dst (thread owns 4 channels).
// Online softmax with finite m-init (NEG_BIG) to avoid inf-inf NaN on merge.
// ---------------------------------------------------------------------------
__global__ __launch_bounds__(128)
void aggregate4(const float* __restrict__ Hm, const float* __restrict__ bias,
                float* __restrict__ out, int n) {
    int t = threadIdx.x;
    int lane = t & 31;
    int lt = t & 63;
    int sub = t >> 6;
    int gh = lt >> 4;
    int dst = blockIdx.x * 2 + sub;
    if (dst >= n) return;

    int beg = g_rowptr[dst];
    int end = g_rowptr[dst + 1];
    float ad_h = g_ad[dst * 4 + gh];

    float m = NEG_BIG, s = 0.0f;
    for (int j = beg + (lane & 15); j < end; j += 16) {
        int src = __ldg(&g_csr_src[j]);
        float e = __ldg(&g_as[src * 4 + gh]) + ad_h;
        e = (e > 0.0f) ? e : 0.2f * e;
        float nm = fmaxf(m, e);
        s = s * __expf(m - nm) + __expf(e - nm);
        m = nm;
    }
#pragma unroll
    for (int o = 8; o; o >>= 1) {
        float om = __shfl_xor_sync(0xffffffffu, m, o);
        float os = __shfl_xor_sync(0xffffffffu, s, o);
        float nm = fmaxf(m, om);
        s = s * __expf(m - nm) + os * __expf(om - nm);
        m = nm;
    }
    float inv = 1.0f / (s + 1e-16f);

    float4 acc = make_float4(0, 0, 0, 0);
    int base = lane & 16;
    for (int c0 = beg; c0 < end; c0 += 16) {
        int cnt = min(16, end - c0);
        int i16 = lane & 15;
        int src = 0; float wv = 0.0f;
        if (i16 < cnt) {
            src = __ldg(&g_csr_src[c0 + i16]);
            float e = __ldg(&g_as[src * 4 + gh]) + ad_h;
            e = (e > 0.0f) ? e : 0.2f * e;
            wv = __expf(e - m) * inv;
        }
        for (int i = 0; i < cnt; i++) {
            int si = __shfl_sync(0xffffffffu, src, base + i);
            float wi = __shfl_sync(0xffffffffu, wv, base + i);
            float4 hv = *(const float4*)&Hm[(size_t)si * 256 + lt * 4];
            acc.x = fmaf(wi, hv.x, acc.x);
            acc.y = fmaf(wi, hv.y, acc.y);
            acc.z = fmaf(wi, hv.z, acc.z);
            acc.w = fmaf(wi, hv.w, acc.w);
        }
    }
    float4 bv = *(const float4*)&bias[lt * 4];
    acc.x = fmaxf(acc.x + bv.x, 0.0f);
    acc.y = fmaxf(acc.y + bv.y, 0.0f);
    acc.z = fmaxf(acc.z + bv.z, 0.0f);
    acc.w = fmaxf(acc.w + bv.w, 0.0f);
    *(float4*)&out[(size_t)dst * 256 + lt * 4] = acc;
}

// ---------------------------------------------------------------------------
// Sync-free fused softmax + aggregation, H=1 (M=64). One warp per dst.
// ---------------------------------------------------------------------------
__global__ __launch_bounds__(128)
void aggregate1(const float* __restrict__ Hm, const float* __restrict__ bias,
                float* __restrict__ out, int n) {
    int t = threadIdx.x;
    int lane = t & 31;
    int wid = t >> 5;
    int dst = blockIdx.x * 4 + wid;
    if (dst >= n) return;

    int beg = g_rowptr[dst];
    int end = g_rowptr[dst + 1];
    float ad_h = g_ad[dst];

    float m = NEG_BIG, s = 0.0f;
    for (int j = beg + lane; j < end; j += 32) {
        int src = __ldg(&g_csr_src[j]);
        float e = __ldg(&g_as[src]) + ad_h;
        e = (e > 0.0f) ? e : 0.2f * e;
        float nm = fmaxf(m, e);
        s = s * __expf(m - nm) + __expf(e - nm);
        m = nm;
    }
#pragma unroll
    for (int o = 16; o; o >>= 1) {
        float om = __shfl_xor_sync(0xffffffffu, m, o);
        float os = __shfl_xor_sync(0xffffffffu, s, o);
        float nm = fmaxf(m, om);
        s = s * __expf(m - nm) + os * __expf(om - nm);
        m = nm;
    }
    float inv = 1.0f / (s + 1e-16f);

    float2 acc = make_float2(0, 0);
    for (int c0 = beg; c0 < end; c0 += 32) {
        int cnt = min(32, end - c0);
        int src = 0; float wv = 0.0f;
        if (lane < cnt) {
            src = __ldg(&g_csr_src[c0 + lane]);
            float e = __ldg(&g_as[src]) + ad_h;
            e = (e > 0.0f) ? e : 0.2f * e;
            wv = __expf(e - m) * inv;
        }
        for (int i = 0; i < cnt; i++) {
            int si = __shfl_sync(0xffffffffu, src, i);
            float wi = __shfl_sync(0xffffffffu, wv, i);
            float2 hv = *(const float2*)&Hm[(size_t)si * 64 + lane * 2];
            acc.x = fmaf(wi, hv.x, acc.x);
            acc.y = fmaf(wi, hv.y, acc.y);
        }
    }
    float2 bv = *(const float2*)&bias[lane * 2];
    acc.x += bv.x;
    acc.y += bv.y;
    *(float2*)&out[(size_t)dst * 64 + lane * 2] = acc;
}

// ---------------------------------------------------------------------------

__global__ void pool_kernel(const float* __restrict__ X, int n) {
    int c = threadIdx.x;   // 64
    float s = 0.0f;
    for (int r = blockIdx.x; r < n; r += gridDim.x)
        s += X[(size_t)r * 64 + c];
    atomicAdd(&g_pool[c], s);
}

__global__ void head_kernel(const float* __restrict__ hw,
                            const float* __restrict__ hb,
                            float* __restrict__ out, int n) {
    int j = threadIdx.x;   // 64
    float inv = 1.0f / (float)n;
    float s = 0.0f;
#pragma unroll
    for (int c = 0; c < 64; c++)
        s = fmaf(g_pool[c] * inv, hw[c * 64 + j], s);
    out[j] = s + hb[j];
}

// ---------------------------------------------------------------------------

extern "C" void kernel_launch(void* const* d_in, const int* in_sizes, int n_in,
                              void* d_out, int out_size) {
    const float* x   = (const float*)d_in[0];
    const void*  ei  = d_in[1];
    const float* W0  = (const float*)d_in[2];
    const float* a0s = (const float*)d_in[3];
    const float* a0d = (const float*)d_in[4];
    const float* b0  = (const float*)d_in[5];
    const float* W1  = (const float*)d_in[6];
    const float* a1s = (const float*)d_in[7];
    const float* a1d = (const float*)d_in[8];
    const float* b1  = (const float*)d_in[9];
    const float* W2  = (const float*)d_in[10];
    const float* a2s = (const float*)d_in[11];
    const float* a2d = (const float*)d_in[12];
    const float* b2  = (const float*)d_in[13];
    const float* hw  = (const float*)d_in[14];
    const float* hb  = (const float*)d_in[15];
    float* out = (float*)d_out;

    int n = in_sizes[0] / 128;
    int E = in_sizes[1] / 2;
    int et = E + n;

    float *bufA, *bufB;
    int *gcursor;
    cudaGetSymbolAddress((void**)&bufA, g_bufA);
    cudaGetSymbolAddress((void**)&bufB, g_bufB);
    cudaGetSymbolAddress((void**)&gcursor, g_cursor);

    int eblocks = (et + 255) / 256;
    if (eblocks > 4096) eblocks = 4096;
    int nb = (n + 1023) / 1024;
    int gy = (n + 127) / 128;
    int ga4 = (n + 1) / 2;
    int ga1 = (n + 3) / 4;

    int histBlocks = 2048;
    int gemmBlocks = 4 * gy;

    // 0. dtype detection (+ zero pool accumulator)
    detect_kernel<<<1, 64>>>(ei, n);

    // 1. zero histogram
    fill_i32<<<(n + 255) / 256, 256>>>(gcursor, 0, n);

    // 2. GEMM layer 0 fused with edge histogram (independent workloads)
    gemm0_hist<<<gemmBlocks + histBlocks, 256>>>(x, W0, bufA, n, a0s, a0d,
                                                 ei, E, gemmBlocks);

    // 3. scan -> rowptr (+cursor), scatter -> CSR
    scan_local<<<nb, 1024>>>(n);
    scan_aux<<<1, 32>>>(nb);
    scan_add<<<nb, 1024>>>(n);
    scatter_kernel<<<eblocks, 256>>>(ei, E, n);

    // ---- Layer 0 aggregate ----
    aggregate4<<<ga4, 128>>>(bufA, b0, bufB, n);

    // ---- Layer 1: 256 -> (4,64) ----
    sgemm_tc<<<dim3(4, gy), 256>>>(bufB, W1, bufA, n, 256, 256, a1s, a1d, 4);
    aggregate4<<<ga4, 128>>>(bufA, b1, bufB, n);

    // ---- Layer 2: 256 -> (1,64) ----
    sgemm_tc<<<dim3(1, gy), 256>>>(bufB, W2, bufA, n, 256, 64, a2s, a2d, 1);
    aggregate1<<<ga1, 128>>>(bufA, b2, bufB, n);

    // ---- Mean pool + head ----
    pool_kernel<<<128, 64>>>(bufB, n);
    head_kernel<<<1, 64>>>(hw, hb, out, n);
}

// round 13
// speedup vs baseline: 3.2621x; 1.2270x over previous
#include <cuda_runtime.h>
#include <math.h>
#include <stdint.h>

// ---------------------------------------------------------------------------
// GAT_23888608101379: 3-layer GAT + mean pool + linear head.
//   - CSR build (histogram fused into GEMM-0, parallel 2-level scan, scatter)
//   - per layer: TF32 tensor-core GEMM (128x64 tile, double-buffered smem,
//                fused alpha epilogue) -> single-pass softmax+aggregate
//                (unnormalized exp accumulate, divide at end; sync-free)
//   - layer 2 aggregate fuses the mean pool; 64x64 head
// ---------------------------------------------------------------------------

#define MAXN 50000
#define MAXE 800000
#define MAXET (MAXE + MAXN)
#define NB_MAX 64

__device__ int   g_is64;
__device__ float g_bufA[MAXN * 256];   // GEMM output h
__device__ float g_bufB[MAXN * 256];   // layer output / next input
__device__ float g_as[MAXN * 4];
__device__ float g_ad[MAXN * 4];
__device__ int   g_rowptr[MAXN + 1];
__device__ int   g_cursor[MAXN];
__device__ int   g_csr_src[MAXET];
__device__ int   g_aux[NB_MAX];
__device__ float g_pool[64];

// ---------------------------------------------------------------------------

__global__ void detect_kernel(const void* ei, int n) {
    // also zeroes the pool accumulator (accumulated later by aggregate1)
    if (threadIdx.x < 64) g_pool[threadIdx.x] = 0.0f;
    if (threadIdx.x == 0) {
        const long long* p = (const long long*)ei;
        int ok = 1;
        for (int i = 0; i < 64; i++) {
            long long v = p[i];
            if (v < 0 || v >= (long long)n) { ok = 0; break; }
        }
        g_is64 = ok;
    }
}

__device__ __forceinline__ void get_edge(const void* ei, int is64, int E, int e,
                                         int& src, int& dst) {
    if (e < E) {
        if (is64) {
            const long long* p = (const long long*)ei;
            src = (int)p[e];
            dst = (int)p[E + e];
        } else {
            const int* p = (const int*)ei;
            src = p[e];
            dst = p[E + e];
        }
    } else {            // self loop
        src = e - E;
        dst = src;
    }
}

__global__ void fill_i32(int* p, int v, int n) {
    int i = blockIdx.x * blockDim.x + threadIdx.x;
    if (i < n) p[i] = v;
}

__device__ void hist_body(const void* ei, int E, int n, int b, int nbk) {
    int is64 = g_is64;
    int et = E + n;
    for (int e = b * 256 + threadIdx.x; e < et; e += nbk * 256) {
        int src, dst;
        get_edge(ei, is64, E, e, src, dst);
        atomicAdd(&g_cursor[dst], 1);
    }
}

// ---- 2-level parallel exclusive scan of counts -> rowptr (+cursor) ----
__global__ void scan_local(int n) {           // grid = nb, block = 1024
    __shared__ int sh[1024];
    int b = blockIdx.x, tid = threadIdx.x;
    int i = b * 1024 + tid;
    int v = (i < n) ? g_cursor[i] : 0;
    sh[tid] = v;
    __syncthreads();
    for (int off = 1; off < 1024; off <<= 1) {
        int t = (tid >= off) ? sh[tid - off] : 0;
        __syncthreads();
        sh[tid] += t;
        __syncthreads();
    }
    if (i < n) g_rowptr[i + 1] = sh[tid];
    if (tid == 1023) g_aux[b] = sh[1023];
}

__global__ void scan_aux(int nb) {            // 1 thread, nb <= 64
    if (threadIdx.x == 0) {
        int s = 0;
        for (int b = 0; b < nb; b++) { int v = g_aux[b]; g_aux[b] = s; s += v; }
        g_rowptr[0] = 0;
    }
}

__global__ void scan_add(int n) {             // grid = nb, block = 1024
    int b = blockIdx.x;
    int i = b * 1024 + threadIdx.x;
    if (i < n) {
        int cnt = g_cursor[i];                 // original per-dst count
        int v = g_rowptr[i + 1] + g_aux[b];    // final rowptr[i+1]
        g_rowptr[i + 1] = v;
        g_cursor[i] = v - cnt;                 // == final rowptr[i]
    }
}

__global__ void scatter_kernel(const void* ei, int E, int n) {
    int is64 = g_is64;
    int et = E + n;
    for (int e = blockIdx.x * blockDim.x + threadIdx.x; e < et;
         e += gridDim.x * blockDim.x) {
        int src, dst;
        get_edge(ei, is64, E, e, src, dst);
        int pos = atomicAdd(&g_cursor[dst], 1);
        g_csr_src[pos] = src;
    }
}

// ---------------------------------------------------------------------------
// TF32 tensor-core GEMM body: C[n,M] = A[n,K] @ B[K,M].
// BM=128, BN=64, BK=16, 256 threads = 8 warps (4 x 2), warp tile 32x32,
// mma.sync.m16n8k8.tf32, double-buffered smem (1 sync per k-tile).
// Fused alpha epilogue (the 64-col tile == one head).
// ---------------------------------------------------------------------------

__device__ __forceinline__ uint32_t f2tf(float f) {
    uint32_t u;
    asm("cvt.rna.tf32.f32 %0, %1;" : "=r"(u) : "f"(f));
    return u;
}

__device__ __forceinline__ void st4_tf(uint32_t* p, float4 v) {
    uint4 u;
    u.x = f2tf(v.x); u.y = f2tf(v.y); u.z = f2tf(v.z); u.w = f2tf(v.w);
    *(uint4*)p = u;
}

__device__ __forceinline__ void mma_tf32(float* d, const uint32_t* a,
                                         const uint32_t* b) {
    asm volatile(
        "mma.sync.aligned.m16n8k8.row.col.f32.tf32.tf32.f32 "
        "{%0,%1,%2,%3}, {%4,%5,%6,%7}, {%8,%9}, {%0,%1,%2,%3};\n"
        : "+f"(d[0]), "+f"(d[1]), "+f"(d[2]), "+f"(d[3])
        : "r"(a[0]), "r"(a[1]), "r"(a[2]), "r"(a[3]), "r"(b[0]), "r"(b[1]));
}

__device__ void sgemm_body(const float* __restrict__ A,
                           const float* __restrict__ B,
                           float* __restrict__ C, int n, int K, int M,
                           const float* __restrict__ avs,
                           const float* __restrict__ avd,
                           int H, int bx, int by) {
    __shared__ uint32_t As[2][128][20];  // [buf][row][k], pitch 20
    __shared__ uint32_t Bs[2][16][72];   // [buf][k][col], pitch 72
    __shared__ float ps_sm[128], pd_sm[128];

    int tid = threadIdx.x;
    int lane = tid & 31, wid = tid >> 5;
    int wm = wid >> 1, wn = wid & 1;
    int rowBase = by * 128;
    int colBase = bx * 64;
    int head = bx;
    int qr = lane >> 2, qc = lane & 3;

    int ar = tid >> 1;
    int aq = (tid & 1) * 8;
    int br = tid >> 4;
    int bc = (tid & 15) * 4;

    int tid128 = tid & 127;
    if (tid < 128) { ps_sm[tid] = 0.0f; pd_sm[tid] = 0.0f; }

    // ---- load tile 0 -> buf 0 ----
    {
        float4 a0v = make_float4(0, 0, 0, 0), a1v = a0v;
        if (rowBase + ar < n) {
            a0v = *(const float4*)&A[(size_t)(rowBase + ar) * K + aq];
            a1v = *(const float4*)&A[(size_t)(rowBase + ar) * K + aq + 4];
        }
        float4 bv = *(const float4*)&B[(size_t)br * M + colBase + bc];
        st4_tf(&As[0][ar][aq], a0v);
        st4_tf(&As[0][ar][aq + 4], a1v);
        st4_tf(&Bs[0][br][bc], bv);
    }
    __syncthreads();

    float acc[2][4][4];
#pragma unroll
    for (int mt = 0; mt < 2; mt++)
#pragma unroll
        for (int nt = 0; nt < 4; nt++)
#pragma unroll
            for (int j = 0; j < 4; j++) acc[mt][nt][j] = 0.0f;

    int nk = K >> 4;
    for (int t = 0; t < nk; t++) {
        int cur = t & 1, nxt = cur ^ 1;
        bool has = (t + 1 < nk);
        float4 aP0, aP1, bP;
        if (has) {
            int k0 = (t + 1) << 4;
            aP0 = make_float4(0, 0, 0, 0); aP1 = aP0;
            if (rowBase + ar < n) {
                aP0 = *(const float4*)&A[(size_t)(rowBase + ar) * K + k0 + aq];
                aP1 = *(const float4*)&A[(size_t)(rowBase + ar) * K + k0 + aq + 4];
            }
            bP = *(const float4*)&B[(size_t)(k0 + br) * M + colBase + bc];
        }
#pragma unroll
        for (int ks = 0; ks < 2; ks++) {
            int kk = ks * 8;
            uint32_t af[2][4];
#pragma unroll
            for (int mt = 0; mt < 2; mt++) {
                int r0 = wm * 32 + mt * 16 + qr;
                int c0 = kk + qc;
                af[mt][0] = As[cur][r0][c0];
                af[mt][1] = As[cur][r0 + 8][c0];
                af[mt][2] = As[cur][r0][c0 + 4];
                af[mt][3] = As[cur][r0 + 8][c0 + 4];
            }
            uint32_t bf[4][2];
#pragma unroll
            for (int nt = 0; nt < 4; nt++) {
                int c = wn * 32 + nt * 8 + qr;
                int r = kk + qc;
                bf[nt][0] = Bs[cur][r][c];
                bf[nt][1] = Bs[cur][r + 4][c];
            }
#pragma unroll
            for (int mt = 0; mt < 2; mt++)
#pragma unroll
                for (int nt = 0; nt < 4; nt++)
                    mma_tf32(acc[mt][nt], af[mt], bf[nt]);
        }
        if (has) {
            st4_tf(&As[nxt][ar][aq], aP0);
            st4_tf(&As[nxt][ar][aq + 4], aP1);
            st4_tf(&Bs[nxt][br][bc], bP);
            __syncthreads();
        }
    }

    // ---- store C tile ----
#pragma unroll
    for (int mt = 0; mt < 2; mt++) {
#pragma unroll
        for (int nt = 0; nt < 4; nt++) {
            int r = rowBase + wm * 32 + mt * 16 + qr;
            int c = colBase + wn * 32 + nt * 8 + qc * 2;
            if (r < n) {
                float2 v0 = make_float2(acc[mt][nt][0], acc[mt][nt][1]);
                *(float2*)&C[(size_t)r * M + c] = v0;
            }
            if (r + 8 < n) {
                float2 v1 = make_float2(acc[mt][nt][2], acc[mt][nt][3]);
                *(float2*)&C[(size_t)(r + 8) * M + c] = v1;
            }
        }
    }

    // ---- fused alpha epilogue ----
    float av_s[8], av_d[8];
#pragma unroll
    for (int nt = 0; nt < 4; nt++)
#pragma unroll
        for (int j = 0; j < 2; j++) {
            int c = wn * 32 + nt * 8 + qc * 2 + j;
            av_s[nt * 2 + j] = __ldg(&avs[head * 64 + c]);
            av_d[nt * 2 + j] = __ldg(&avd[head * 64 + c]);
        }
#pragma unroll
    for (int mt = 0; mt < 2; mt++) {
#pragma unroll
        for (int half = 0; half < 2; half++) {
            float ps = 0.0f, pd = 0.0f;
#pragma unroll
            for (int nt = 0; nt < 4; nt++)
#pragma unroll
                for (int j = 0; j < 2; j++) {
                    float v = acc[mt][nt][half * 2 + j];
                    ps = fmaf(v, av_s[nt * 2 + j], ps);
                    pd = fmaf(v, av_d[nt * 2 + j], pd);
                }
            ps += __shfl_xor_sync(0xffffffffu, ps, 1);
            ps += __shfl_xor_sync(0xffffffffu, ps, 2);
            pd += __shfl_xor_sync(0xffffffffu, pd, 1);
            pd += __shfl_xor_sync(0xffffffffu, pd, 2);
            if (qc == 0) {
                int rloc = wm * 32 + mt * 16 + qr + half * 8;
                atomicAdd(&ps_sm[rloc], ps);
                atomicAdd(&pd_sm[rloc], pd);
            }
        }
    }
    __syncthreads();
    if (tid < 128) {
        int r = rowBase + tid128;
        if (r < n) {
            g_as[r * H + head] = ps_sm[tid128];
            g_ad[r * H + head] = pd_sm[tid128];
        }
    }
}

__global__ __launch_bounds__(256)
void sgemm_tc(const float* __restrict__ A, const float* __restrict__ B,
              float* __restrict__ C, int n, int K, int M,
              const float* __restrict__ avs, const float* __restrict__ avd,
              int H) {
    sgemm_body(A, B, C, n, K, M, avs, avd, H, blockIdx.x, blockIdx.y);
}

// Fused: GEMM-0 (blocks [0, gemmBlocks)) + edge histogram (remaining blocks).
__global__ __launch_bounds__(256)
void gemm0_hist(const float* __restrict__ A, const float* __restrict__ B,
                float* __restrict__ C, int n,
                const float* __restrict__ avs, const float* __restrict__ avd,
                const void* ei, int E, int gemmBlocks) {
    int b = blockIdx.x;
    if (b < gemmBlocks) {
        sgemm_body(A, B, C, n, 128, 256, avs, avd, 4, b & 3, b >> 2);
    } else {
        hist_body(ei, E, n, b - gemmBlocks, gridDim.x - gemmBlocks);
    }
}

// ---------------------------------------------------------------------------
// Single-pass softmax + aggregation, H=4 (M=256).
// 128 threads = 2 dst nodes; 64 threads per dst (thread owns 4 channels).
// Softmax is shift-invariant and e-scores here are O(1), so we accumulate
// UNNORMALIZED  acc = sum_e exp(e_i) h_i  and  s = sum_e exp(e_i), dividing
// at the end. One pass over the CSR row; gather unrolled x2 for MLP.
// ---------------------------------------------------------------------------
__global__ __launch_bounds__(128)
void aggregate4(const float* __restrict__ Hm, const float* __restrict__ bias,
                float* __restrict__ out, int n) {
    int t = threadIdx.x;
    int lane = t & 31;
    int lt = t & 63;
    int sub = t >> 6;
    int gh = lt >> 4;
    int dst = blockIdx.x * 2 + sub;
    if (dst >= n) return;      // no block-wide sync in this kernel

    int beg = g_rowptr[dst];
    int end = g_rowptr[dst + 1];
    float ad_h = g_ad[dst * 4 + gh];

    float4 acc0 = make_float4(0, 0, 0, 0);
    float4 acc1 = make_float4(0, 0, 0, 0);
    float sp = 0.0f;
    int base = lane & 16;
    int i16 = lane & 15;

    for (int c0 = beg; c0 < end; c0 += 16) {
        int cnt = min(16, end - c0);
        int src = 0; float wv = 0.0f;
        if (i16 < cnt) {
            src = __ldg(&g_csr_src[c0 + i16]);
            float e = __ldg(&g_as[src * 4 + gh]) + ad_h;
            e = (e > 0.0f) ? e : 0.2f * e;
            wv = __expf(e);
        }
        sp += wv;
        int i = 0;
        for (; i + 1 < cnt; i += 2) {
            int s0 = __shfl_sync(0xffffffffu, src, base + i);
            float w0 = __shfl_sync(0xffffffffu, wv, base + i);
            int s1 = __shfl_sync(0xffffffffu, src, base + i + 1);
            float w1 = __shfl_sync(0xffffffffu, wv, base + i + 1);
            float4 h0 = *(const float4*)&Hm[(size_t)s0 * 256 + lt * 4];
            float4 h1 = *(const float4*)&Hm[(size_t)s1 * 256 + lt * 4];
            acc0.x = fmaf(w0, h0.x, acc0.x);
            acc0.y = fmaf(w0, h0.y, acc0.y);
            acc0.z = fmaf(w0, h0.z, acc0.z);
            acc0.w = fmaf(w0, h0.w, acc0.w);
            acc1.x = fmaf(w1, h1.x, acc1.x);
            acc1.y = fmaf(w1, h1.y, acc1.y);
            acc1.z = fmaf(w1, h1.z, acc1.z);
            acc1.w = fmaf(w1, h1.w, acc1.w);
        }
        if (i < cnt) {
            int s0 = __shfl_sync(0xffffffffu, src, base + i);
            float w0 = __shfl_sync(0xffffffffu, wv, base + i);
            float4 h0 = *(const float4*)&Hm[(size_t)s0 * 256 + lt * 4];
            acc0.x = fmaf(w0, h0.x, acc0.x);
            acc0.y = fmaf(w0, h0.y, acc0.y);
            acc0.z = fmaf(w0, h0.z, acc0.z);
            acc0.w = fmaf(w0, h0.w, acc0.w);
        }
    }
    // reduce s over the 16-lane group (xor stays within the group)
#pragma unroll
    for (int o = 8; o; o >>= 1) sp += __shfl_xor_sync(0xffffffffu, sp, o);
    float inv = 1.0f / (sp + 1e-16f);

    float4 bv = *(const float4*)&bias[lt * 4];
    float4 r;
    r.x = fmaxf(fmaf(acc0.x + acc1.x, inv, bv.x), 0.0f);
    r.y = fmaxf(fmaf(acc0.y + acc1.y, inv, bv.y), 0.0f);
    r.z = fmaxf(fmaf(acc0.z + acc1.z, inv, bv.z), 0.0f);
    r.w = fmaxf(fmaf(acc0.w + acc1.w, inv, bv.w), 0.0f);
    *(float4*)&out[(size_t)dst * 256 + lt * 4] = r;
}

// ---------------------------------------------------------------------------
// Single-pass softmax + aggregation + MEAN POOL, H=1 (M=64).
// One warp per dst, 4 dst per block; lane owns 2 channels. The layer-2
// output is only consumed by the global mean, so we never write it out:
// block-reduce into smem, one global atomicAdd per channel per block.
// ---------------------------------------------------------------------------
__global__ __launch_bounds__(128)
void aggregate1(const float* __restrict__ Hm, const float* __restrict__ bias,
                int n) {
    __shared__ float psum[64];
    int t = threadIdx.x;
    int lane = t & 31;
    int wid = t >> 5;
    if (t < 64) psum[t] = 0.0f;
    __syncthreads();

    int dst = blockIdx.x * 4 + wid;
    if (dst < n) {
        int beg = g_rowptr[dst];
        int end = g_rowptr[dst + 1];
        float ad_h = g_ad[dst];

        float2 acc0 = make_float2(0, 0), acc1 = make_float2(0, 0);
        float sp = 0.0f;

        for (int c0 = beg; c0 < end; c0 += 32) {
            int cnt = min(32, end - c0);
            int src = 0; float wv = 0.0f;
            if (lane < cnt) {
                src = __ldg(&g_csr_src[c0 + lane]);
                float e = __ldg(&g_as[src]) + ad_h;
                e = (e > 0.0f) ? e : 0.2f * e;
                wv = __expf(e);
            }
            sp += wv;
            int i = 0;
            for (; i + 1 < cnt; i += 2) {
                int s0 = __shfl_sync(0xffffffffu, src, i);
                float w0 = __shfl_sync(0xffffffffu, wv, i);
                int s1 = __shfl_sync(0xffffffffu, src, i + 1);
                float w1 = __shfl_sync(0xffffffffu, wv, i + 1);
                float2 h0 = *(const float2*)&Hm[(size_t)s0 * 64 + lane * 2];
                float2 h1 = *(const float2*)&Hm[(size_t)s1 * 64 + lane * 2];
                acc0.x = fmaf(w0, h0.x, acc0.x);
                acc0.y = fmaf(w0, h0.y, acc0.y);
                acc1.x = fmaf(w1, h1.x, acc1.x);
                acc1.y = fmaf(w1, h1.y, acc1.y);
            }
            if (i < cnt) {
                int s0 = __shfl_sync(0xffffffffu, src, i);
                float w0 = __shfl_sync(0xffffffffu, wv, i);
                float2 h0 = *(const float2*)&Hm[(size_t)s0 * 64 + lane * 2];
                acc0.x = fmaf(w0, h0.x, acc0.x);
                acc0.y = fmaf(w0, h0.y, acc0.y);
            }
        }
#pragma unroll
        for (int o = 16; o; o >>= 1) sp += __shfl_xor_sync(0xffffffffu, sp, o);
        float inv = 1.0f / (sp + 1e-16f);

        float2 bv = *(const float2*)&bias[lane * 2];
        float ox = fmaf(acc0.x + acc1.x, inv, bv.x);
        float oy = fmaf(acc0.y + acc1.y, inv, bv.y);
        atomicAdd(&psum[lane * 2], ox);
        atomicAdd(&psum[lane * 2 + 1], oy);
    }
    __syncthreads();
    if (t < 64) atomicAdd(&g_pool[t], psum[t]);
}

// ---------------------------------------------------------------------------

__global__ void head_kernel(const float* __restrict__ hw,
                            const float* __restrict__ hb,
                            float* __restrict__ out, int n) {
    int j = threadIdx.x;   // 64
    float inv = 1.0f / (float)n;
    float s = 0.0f;
#pragma unroll
    for (int c = 0; c < 64; c++)
        s = fmaf(g_pool[c] * inv, hw[c * 64 + j], s);
    out[j] = s + hb[j];
}

// ---------------------------------------------------------------------------

extern "C" void kernel_launch(void* const* d_in, const int* in_sizes, int n_in,
                              void* d_out, int out_size) {
    const float* x   = (const float*)d_in[0];
    const void*  ei  = d_in[1];
    const float* W0  = (const float*)d_in[2];
    const float* a0s = (const float*)d_in[3];
    const float* a0d = (const float*)d_in[4];
    const float* b0  = (const float*)d_in[5];
    const float* W1  = (const float*)d_in[6];
    const float* a1s = (const float*)d_in[7];
    const float* a1d = (const float*)d_in[8];
    const float* b1  = (const float*)d_in[9];
    const float* W2  = (const float*)d_in[10];
    const float* a2s = (const float*)d_in[11];
    const float* a2d = (const float*)d_in[12];
    const float* b2  = (const float*)d_in[13];
    const float* hw  = (const float*)d_in[14];
    const float* hb  = (const float*)d_in[15];
    float* out = (float*)d_out;

    int n = in_sizes[0] / 128;
    int E = in_sizes[1] / 2;
    int et = E + n;

    float *bufA, *bufB;
    int *gcursor;
    cudaGetSymbolAddress((void**)&bufA, g_bufA);
    cudaGetSymbolAddress((void**)&bufB, g_bufB);
    cudaGetSymbolAddress((void**)&gcursor, g_cursor);

    int eblocks = (et + 255) / 256;
    if (eblocks > 4096) eblocks = 4096;
    int nb = (n + 1023) / 1024;
    int gy = (n + 127) / 128;
    int ga4 = (n + 1) / 2;
    int ga1 = (n + 3) / 4;

    int histBlocks = 2048;
    int gemmBlocks = 4 * gy;

    // 0. dtype detection (+ zero pool accumulator)
    detect_kernel<<<1, 64>>>(ei, n);

    // 1. zero histogram
    fill_i32<<<(n + 255) / 256, 256>>>(gcursor, 0, n);

    // 2. GEMM layer 0 fused with edge histogram (independent workloads)
    gemm0_hist<<<gemmBlocks + histBlocks, 256>>>(x, W0, bufA, n, a0s, a0d,
                                                 ei, E, gemmBlocks);

    // 3. scan -> rowptr (+cursor), scatter -> CSR
    scan_local<<<nb, 1024>>>(n);
    scan_aux<<<1, 32>>>(nb);
    scan_add<<<nb, 1024>>>(n);
    scatter_kernel<<<eblocks, 256>>>(ei, E, n);

    // ---- Layer 0 aggregate ----
    aggregate4<<<ga4, 128>>>(bufA, b0, bufB, n);

    // ---- Layer 1: 256 -> (4,64) ----
    sgemm_tc<<<dim3(4, gy), 256>>>(bufB, W1, bufA, n, 256, 256, a1s, a1d, 4);
    aggregate4<<<ga4, 128>>>(bufA, b1, bufB, n);

    // ---- Layer 2: 256 -> (1,64) ----
    sgemm_tc<<<dim3(1, gy), 256>>>(bufB, W2, bufA, n, 256, 64, a2s, a2d, 1);
    aggregate1<<<ga1, 128>>>(bufA, b2, n);   // fuses mean pool

    // ---- Head ----
    head_kernel<<<1, 64>>>(hw, hb, out, n);
}

// round 14
// speedup vs baseline: 3.4983x; 1.0724x over previous
#include <cuda_runtime.h>
#include <cuda_bf16.h>
#include <math.h>
#include <stdint.h>

// ---------------------------------------------------------------------------
// GAT_23888608101379: 3-layer GAT + mean pool + linear head.
//   - CSR build (histogram fused into GEMM-0, parallel 2-level scan, scatter)
//   - per layer: TF32 tensor-core GEMM (128x64 tile, double-buffered smem,
//                fused alpha epilogue, BF16X2 feature store)
//                -> single-pass softmax+aggregate reading bf16 (halved bytes)
//   - layer 2 aggregate fuses the mean pool; 64x64 head
// ---------------------------------------------------------------------------

#define MAXN 50000
#define MAXE 800000
#define MAXET (MAXE + MAXN)
#define NB_MAX 64

__device__ int      g_is64;
__device__ uint32_t g_h16[MAXN * 128];   // GEMM output h as bf16x2 (gather src)
__device__ float    g_bufB[MAXN * 256];  // aggregate output / next GEMM input
__device__ float    g_as[MAXN * 4];
__device__ float    g_ad[MAXN * 4];
__device__ int      g_rowptr[MAXN + 1];
__device__ int      g_cursor[MAXN];
__device__ int      g_csr_src[MAXET];
__device__ int      g_aux[NB_MAX];
__device__ float    g_pool[64];

// ---------------------------------------------------------------------------

__global__ void detect_kernel(const void* ei, int n) {
    if (threadIdx.x < 64) g_pool[threadIdx.x] = 0.0f;
    if (threadIdx.x == 0) {
        const long long* p = (const long long*)ei;
        int ok = 1;
        for (int i = 0; i < 64; i++) {
            long long v = p[i];
            if (v < 0 || v >= (long long)n) { ok = 0; break; }
        }
        g_is64 = ok;
    }
}

__device__ __forceinline__ void get_edge(const void* ei, int is64, int E, int e,
                                         int& src, int& dst) {
    if (e < E) {
        if (is64) {
            const long long* p = (const long long*)ei;
            src = (int)p[e];
            dst = (int)p[E + e];
        } else {
            const int* p = (const int*)ei;
            src = p[e];
            dst = p[E + e];
        }
    } else {            // self loop
        src = e - E;
        dst = src;
    }
}

__global__ void fill_i32(int* p, int v, int n) {
    int i = blockIdx.x * blockDim.x + threadIdx.x;
    if (i < n) p[i] = v;
}

__device__ void hist_body(const void* ei, int E, int n, int b, int nbk) {
    int is64 = g_is64;
    int et = E + n;
    for (int e = b * 256 + threadIdx.x; e < et; e += nbk * 256) {
        int src, dst;
        get_edge(ei, is64, E, e, src, dst);
        atomicAdd(&g_cursor[dst], 1);
    }
}

// ---- 2-level parallel exclusive scan of counts -> rowptr (+cursor) ----
__global__ void scan_local(int n) {           // grid = nb, block = 1024
    __shared__ int sh[1024];
    int b = blockIdx.x, tid = threadIdx.x;
    int i = b * 1024 + tid;
    int v = (i < n) ? g_cursor[i] : 0;
    sh[tid] = v;
    __syncthreads();
    for (int off = 1; off < 1024; off <<= 1) {
        int t = (tid >= off) ? sh[tid - off] : 0;
        __syncthreads();
        sh[tid] += t;
        __syncthreads();
    }
    if (i < n) g_rowptr[i + 1] = sh[tid];
    if (tid == 1023) g_aux[b] = sh[1023];
}

__global__ void scan_aux(int nb) {            // 1 thread, nb <= 64
    if (threadIdx.x == 0) {
        int s = 0;
        for (int b = 0; b < nb; b++) { int v = g_aux[b]; g_aux[b] = s; s += v; }
        g_rowptr[0] = 0;
    }
}

__global__ void scan_add(int n) {             // grid = nb, block = 1024
    int b = blockIdx.x;
    int i = b * 1024 + threadIdx.x;
    if (i < n) {
        int cnt = g_cursor[i];                 // original per-dst count
        int v = g_rowptr[i + 1] + g_aux[b];    // final rowptr[i+1]
        g_rowptr[i + 1] = v;
        g_cursor[i] = v - cnt;                 // == final rowptr[i]
    }
}

__global__ void scatter_kernel(const void* ei, int E, int n) {
    int is64 = g_is64;
    int et = E + n;
    for (int e = blockIdx.x * blockDim.x + threadIdx.x; e < et;
         e += gridDim.x * blockDim.x) {
        int src, dst;
        get_edge(ei, is64, E, e, src, dst);
        int pos = atomicAdd(&g_cursor[dst], 1);
        g_csr_src[pos] = src;
    }
}

// ---------------------------------------------------------------------------
// TF32 tensor-core GEMM body: C16[n, M/2] (bf16x2) = A[n,K] @ B[K,M].
// BM=128, BN=64, BK=16, 256 threads = 8 warps (4 x 2), warp tile 32x32,
// mma.sync.m16n8k8.tf32, double-buffered smem (1 sync per k-tile).
// Fused alpha epilogue from fp32 accumulators (the 64-col tile == one head).
// ---------------------------------------------------------------------------

__device__ __forceinline__ uint32_t f2tf(float f) {
    uint32_t u;
    asm("cvt.rna.tf32.f32 %0, %1;" : "=r"(u) : "f"(f));
    return u;
}

__device__ __forceinline__ void st4_tf(uint32_t* p, float4 v) {
    uint4 u;
    u.x = f2tf(v.x); u.y = f2tf(v.y); u.z = f2tf(v.z); u.w = f2tf(v.w);
    *(uint4*)p = u;
}

__device__ __forceinline__ uint32_t pack_bf16x2(float lo, float hi) {
    __nv_bfloat162 h = __floats2bfloat162_rn(lo, hi);   // .x=lo, .y=hi
    return *(uint32_t*)&h;
}

__device__ __forceinline__ void mma_tf32(float* d, const uint32_t* a,
                                         const uint32_t* b) {
    asm volatile(
        "mma.sync.aligned.m16n8k8.row.col.f32.tf32.tf32.f32 "
        "{%0,%1,%2,%3}, {%4,%5,%6,%7}, {%8,%9}, {%0,%1,%2,%3};\n"
        : "+f"(d[0]), "+f"(d[1]), "+f"(d[2]), "+f"(d[3])
        : "r"(a[0]), "r"(a[1]), "r"(a[2]), "r"(a[3]), "r"(b[0]), "r"(b[1]));
}

__device__ void sgemm_body(const float* __restrict__ A,
                           const float* __restrict__ B,
                           uint32_t* __restrict__ C16, int n, int K, int M,
                           const float* __restrict__ avs,
                           const float* __restrict__ avd,
                           int H, int bx, int by) {
    __shared__ uint32_t As[2][128][20];  // [buf][row][k], pitch 20
    __shared__ uint32_t Bs[2][16][72];   // [buf][k][col], pitch 72
    __shared__ float ps_sm[128], pd_sm[128];

    int tid = threadIdx.x;
    int lane = tid & 31, wid = tid >> 5;
    int wm = wid >> 1, wn = wid & 1;
    int rowBase = by * 128;
    int colBase = bx * 64;
    int head = bx;
    int qr = lane >> 2, qc = lane & 3;
    int Mh = M >> 1;

    int ar = tid >> 1;
    int aq = (tid & 1) * 8;
    int br = tid >> 4;
    int bc = (tid & 15) * 4;

    int tid128 = tid & 127;
    if (tid < 128) { ps_sm[tid] = 0.0f; pd_sm[tid] = 0.0f; }

    // ---- load tile 0 -> buf 0 ----
    {
        float4 a0v = make_float4(0, 0, 0, 0), a1v = a0v;
        if (rowBase + ar < n) {
            a0v = *(const float4*)&A[(size_t)(rowBase + ar) * K + aq];
            a1v = *(const float4*)&A[(size_t)(rowBase + ar) * K + aq + 4];
        }
        float4 bv = *(const float4*)&B[(size_t)br * M + colBase + bc];
        st4_tf(&As[0][ar][aq], a0v);
        st4_tf(&As[0][ar][aq + 4], a1v);
        st4_tf(&Bs[0][br][bc], bv);
    }
    __syncthreads();

    float acc[2][4][4];
#pragma unroll
    for (int mt = 0; mt < 2; mt++)
#pragma unroll
        for (int nt = 0; nt < 4; nt++)
#pragma unroll
            for (int j = 0; j < 4; j++) acc[mt][nt][j] = 0.0f;

    int nk = K >> 4;
    for (int t = 0; t < nk; t++) {
        int cur = t & 1, nxt = cur ^ 1;
        bool has = (t + 1 < nk);
        float4 aP0, aP1, bP;
        if (has) {
            int k0 = (t + 1) << 4;
            aP0 = make_float4(0, 0, 0, 0); aP1 = aP0;
            if (rowBase + ar < n) {
                aP0 = *(const float4*)&A[(size_t)(rowBase + ar) * K + k0 + aq];
                aP1 = *(const float4*)&A[(size_t)(rowBase + ar) * K + k0 + aq + 4];
            }
            bP = *(const float4*)&B[(size_t)(k0 + br) * M + colBase + bc];
        }
#pragma unroll
        for (int ks = 0; ks < 2; ks++) {
            int kk = ks * 8;
            uint32_t af[2][4];
#pragma unroll
            for (int mt = 0; mt < 2; mt++) {
                int r0 = wm * 32 + mt * 16 + qr;
                int c0 = kk + qc;
                af[mt][0] = As[cur][r0][c0];
                af[mt][1] = As[cur][r0 + 8][c0];
                af[mt][2] = As[cur][r0][c0 + 4];
                af[mt][3] = As[cur][r0 + 8][c0 + 4];
            }
            uint32_t bf[4][2];
#pragma unroll
            for (int nt = 0; nt < 4; nt++) {
                int c = wn * 32 + nt * 8 + qr;
                int r = kk + qc;
                bf[nt][0] = Bs[cur][r][c];
                bf[nt][1] = Bs[cur][r + 4][c];
            }
#pragma unroll
            for (int mt = 0; mt < 2; mt++)
#pragma unroll
                for (int nt = 0; nt < 4; nt++)
                    mma_tf32(acc[mt][nt], af[mt], bf[nt]);
        }
        if (has) {
            st4_tf(&As[nxt][ar][aq], aP0);
            st4_tf(&As[nxt][ar][aq + 4], aP1);
            st4_tf(&Bs[nxt][br][bc], bP);
            __syncthreads();
        }
    }

    // ---- store C tile as bf16x2 (adjacent column pair per word) ----
#pragma unroll
    for (int mt = 0; mt < 2; mt++) {
#pragma unroll
        for (int nt = 0; nt < 4; nt++) {
            int r = rowBase + wm * 32 + mt * 16 + qr;
            int c = colBase + wn * 32 + nt * 8 + qc * 2;   // even
            if (r < n)
                C16[(size_t)r * Mh + (c >> 1)] =
                    pack_bf16x2(acc[mt][nt][0], acc[mt][nt][1]);
            if (r + 8 < n)
                C16[(size_t)(r + 8) * Mh + (c >> 1)] =
                    pack_bf16x2(acc[mt][nt][2], acc[mt][nt][3]);
        }
    }

    // ---- fused alpha epilogue (fp32 accumulators) ----
    float av_s[8], av_d[8];
#pragma unroll
    for (int nt = 0; nt < 4; nt++)
#pragma unroll
        for (int j = 0; j < 2; j++) {
            int c = wn * 32 + nt * 8 + qc * 2 + j;
            av_s[nt * 2 + j] = __ldg(&avs[head * 64 + c]);
            av_d[nt * 2 + j] = __ldg(&avd[head * 64 + c]);
        }
#pragma unroll
    for (int mt = 0; mt < 2; mt++) {
#pragma unroll
        for (int half = 0; half < 2; half++) {
            float ps = 0.0f, pd = 0.0f;
#pragma unroll
            for (int nt = 0; nt < 4; nt++)
#pragma unroll
                for (int j = 0; j < 2; j++) {
                    float v = acc[mt][nt][half * 2 + j];
                    ps = fmaf(v, av_s[nt * 2 + j], ps);
                    pd = fmaf(v, av_d[nt * 2 + j], pd);
                }
            ps += __shfl_xor_sync(0xffffffffu, ps, 1);
            ps += __shfl_xor_sync(0xffffffffu, ps, 2);
            pd += __shfl_xor_sync(0xffffffffu, pd, 1);
            pd += __shfl_xor_sync(0xffffffffu, pd, 2);
            if (qc == 0) {
                int rloc = wm * 32 + mt * 16 + qr + half * 8;
                atomicAdd(&ps_sm[rloc], ps);
                atomicAdd(&pd_sm[rloc], pd);
            }
        }
    }
    __syncthreads();
    if (tid < 128) {
        int r = rowBase + tid128;
        if (r < n) {
            g_as[r * H + head] = ps_sm[tid128];
            g_ad[r * H + head] = pd_sm[tid128];
        }
    }
}

__global__ __launch_bounds__(256)
void sgemm_tc(const float* __restrict__ A, const float* __restrict__ B,
              uint32_t* __restrict__ C16, int n, int K, int M,
              const float* __restrict__ avs, const float* __restrict__ avd,
              int H) {
    sgemm_body(A, B, C16, n, K, M, avs, avd, H, blockIdx.x, blockIdx.y);
}

// Fused: GEMM-0 (blocks [0, gemmBlocks)) + edge histogram (remaining blocks).
__global__ __launch_bounds__(256)
void gemm0_hist(const float* __restrict__ A, const float* __restrict__ B,
                uint32_t* __restrict__ C16, int n,
                const float* __restrict__ avs, const float* __restrict__ avd,
                const void* ei, int E, int gemmBlocks) {
    int b = blockIdx.x;
    if (b < gemmBlocks) {
        sgemm_body(A, B, C16, n, 128, 256, avs, avd, 4, b & 3, b >> 2);
    } else {
        hist_body(ei, E, n, b - gemmBlocks, gridDim.x - gemmBlocks);
    }
}

// ---------------------------------------------------------------------------
// Single-pass softmax + aggregation, H=4 (M=256), bf16 gather source.
// 128 threads = 2 dst nodes; 64 threads per dst (thread owns 4 channels =
// 2 bf16x2 words). Unnormalized exp accumulate, divide at end.
// ---------------------------------------------------------------------------
__global__ __launch_bounds__(128)
void aggregate4(const uint32_t* __restrict__ H16,
                const float* __restrict__ bias,
                float* __restrict__ out, int n) {
    int t = threadIdx.x;
    int lane = t & 31;
    int lt = t & 63;
    int sub = t >> 6;
    int gh = lt >> 4;
    int dst = blockIdx.x * 2 + sub;
    if (dst >= n) return;      // no block-wide sync in this kernel

    int beg = g_rowptr[dst];
    int end = g_rowptr[dst + 1];
    float ad_h = g_ad[dst * 4 + gh];

    float4 acc0 = make_float4(0, 0, 0, 0);
    float4 acc1 = make_float4(0, 0, 0, 0);
    float sp = 0.0f;
    int base = lane & 16;
    int i16 = lane & 15;

    for (int c0 = beg; c0 < end; c0 += 16) {
        int cnt = min(16, end - c0);
        int src = 0; float wv = 0.0f;
        if (i16 < cnt) {
            src = __ldg(&g_csr_src[c0 + i16]);
            float e = __ldg(&g_as[src * 4 + gh]) + ad_h;
            e = (e > 0.0f) ? e : 0.2f * e;
            wv = __expf(e);
        }
        sp += wv;
        int i = 0;
        for (; i + 1 < cnt; i += 2) {
            int s0 = __shfl_sync(0xffffffffu, src, base + i);
            float w0 = __shfl_sync(0xffffffffu, wv, base + i);
            int s1 = __shfl_sync(0xffffffffu, src, base + i + 1);
            float w1 = __shfl_sync(0xffffffffu, wv, base + i + 1);
            uint2 p0 = *(const uint2*)&H16[(size_t)s0 * 128 + lt * 2];
            uint2 p1 = *(const uint2*)&H16[(size_t)s1 * 128 + lt * 2];
            float2 a0 = __bfloat1622float2(*(__nv_bfloat162*)&p0.x);
            float2 b0 = __bfloat1622float2(*(__nv_bfloat162*)&p0.y);
            float2 a1 = __bfloat1622float2(*(__nv_bfloat162*)&p1.x);
            float2 b1 = __bfloat1622float2(*(__nv_bfloat162*)&p1.y);
            acc0.x = fmaf(w0, a0.x, acc0.x);
            acc0.y = fmaf(w0, a0.y, acc0.y);
            acc0.z = fmaf(w0, b0.x, acc0.z);
            acc0.w = fmaf(w0, b0.y, acc0.w);
            acc1.x = fmaf(w1, a1.x, acc1.x);
            acc1.y = fmaf(w1, a1.y, acc1.y);
            acc1.z = fmaf(w1, b1.x, acc1.z);
            acc1.w = fmaf(w1, b1.y, acc1.w);
        }
        if (i < cnt) {
            int s0 = __shfl_sync(0xffffffffu, src, base + i);
            float w0 = __shfl_sync(0xffffffffu, wv, base + i);
            uint2 p0 = *(const uint2*)&H16[(size_t)s0 * 128 + lt * 2];
            float2 a0 = __bfloat1622float2(*(__nv_bfloat162*)&p0.x);
            float2 b0 = __bfloat1622float2(*(__nv_bfloat162*)&p0.y);
            acc0.x = fmaf(w0, a0.x, acc0.x);
            acc0.y = fmaf(w0, a0.y, acc0.y);
            acc0.z = fmaf(w0, b0.x, acc0.z);
            acc0.w = fmaf(w0, b0.y, acc0.w);
        }
    }
#pragma unroll
    for (int o = 8; o; o >>= 1) sp += __shfl_xor_sync(0xffffffffu, sp, o);
    float inv = 1.0f / (sp + 1e-16f);

    float4 bv = *(const float4*)&bias[lt * 4];
    float4 r;
    r.x = fmaxf(fmaf(acc0.x + acc1.x, inv, bv.x), 0.0f);
    r.y = fmaxf(fmaf(acc0.y + acc1.y, inv, bv.y), 0.0f);
    r.z = fmaxf(fmaf(acc0.z + acc1.z, inv, bv.z), 0.0f);
    r.w = fmaxf(fmaf(acc0.w + acc1.w, inv, bv.w), 0.0f);
    *(float4*)&out[(size_t)dst * 256 + lt * 4] = r;
}

// ---------------------------------------------------------------------------
// Single-pass softmax + aggregation + MEAN POOL, H=1 (M=64), bf16 source.
// One warp per dst, 4 dst per block; lane owns 2 channels (one bf16x2 word).
// ---------------------------------------------------------------------------
__global__ __launch_bounds__(128)
void aggregate1(const uint32_t* __restrict__ H16,
                const float* __restrict__ bias, int n) {
    __shared__ float psum[64];
    int t = threadIdx.x;
    int lane = t & 31;
    int wid = t >> 5;
    if (t < 64) psum[t] = 0.0f;
    __syncthreads();

    int dst = blockIdx.x * 4 + wid;
    if (dst < n) {
        int beg = g_rowptr[dst];
        int end = g_rowptr[dst + 1];
        float ad_h = g_ad[dst];

        float2 acc0 = make_float2(0, 0), acc1 = make_float2(0, 0);
        float sp = 0.0f;

        for (int c0 = beg; c0 < end; c0 += 32) {
            int cnt = min(32, end - c0);
            int src = 0; float wv = 0.0f;
            if (lane < cnt) {
                src = __ldg(&g_csr_src[c0 + lane]);
                float e = __ldg(&g_as[src]) + ad_h;
                e = (e > 0.0f) ? e : 0.2f * e;
                wv = __expf(e);
            }
            sp += wv;
            int i = 0;
            for (; i + 1 < cnt; i += 2) {
                int s0 = __shfl_sync(0xffffffffu, src, i);
                float w0 = __shfl_sync(0xffffffffu, wv, i);
                int s1 = __shfl_sync(0xffffffffu, src, i + 1);
                float w1 = __shfl_sync(0xffffffffu, wv, i + 1);
                uint32_t q0 = __ldg(&H16[(size_t)s0 * 32 + lane]);
                uint32_t q1 = __ldg(&H16[(size_t)s1 * 32 + lane]);
                float2 h0 = __bfloat1622float2(*(__nv_bfloat162*)&q0);
                float2 h1 = __bfloat1622float2(*(__nv_bfloat162*)&q1);
                acc0.x = fmaf(w0, h0.x, acc0.x);
                acc0.y = fmaf(w0, h0.y, acc0.y);
                acc1.x = fmaf(w1, h1.x, acc1.x);
                acc1.y = fmaf(w1, h1.y, acc1.y);
            }
            if (i < cnt) {
                int s0 = __shfl_sync(0xffffffffu, src, i);
                float w0 = __shfl_sync(0xffffffffu, wv, i);
                uint32_t q0 = __ldg(&H16[(size_t)s0 * 32 + lane]);
                float2 h0 = __bfloat1622float2(*(__nv_bfloat162*)&q0);
                acc0.x = fmaf(w0, h0.x, acc0.x);
                acc0.y = fmaf(w0, h0.y, acc0.y);
            }
        }
#pragma unroll
        for (int o = 16; o; o >>= 1) sp += __shfl_xor_sync(0xffffffffu, sp, o);
        float inv = 1.0f / (sp + 1e-16f);

        float2 bv = *(const float2*)&bias[lane * 2];
        float ox = fmaf(acc0.x + acc1.x, inv, bv.x);
        float oy = fmaf(acc0.y + acc1.y, inv, bv.y);
        atomicAdd(&psum[lane * 2], ox);
        atomicAdd(&psum[lane * 2 + 1], oy);
    }
    __syncthreads();
    if (t < 64) atomicAdd(&g_pool[t], psum[t]);
}

// ---------------------------------------------------------------------------

__global__ void head_kernel(const float* __restrict__ hw,
                            const float* __restrict__ hb,
                            float* __restrict__ out, int n) {
    int j = threadIdx.x;   // 64
    float inv = 1.0f / (float)n;
    float s = 0.0f;
#pragma unroll
    for (int c = 0; c < 64; c++)
        s = fmaf(g_pool[c] * inv, hw[c * 64 + j], s);
    out[j] = s + hb[j];
}

// ---------------------------------------------------------------------------

extern "C" void kernel_launch(void* const* d_in, const int* in_sizes, int n_in,
                              void* d_out, int out_size) {
    const float* x   = (const float*)d_in[0];
    const void*  ei  = d_in[1];
    const float* W0  = (const float*)d_in[2];
    const float* a0s = (const float*)d_in[3];
    const float* a0d = (const float*)d_in[4];
    const float* b0  = (const float*)d_in[5];
    const float* W1  = (const float*)d_in[6];
    const float* a1s = (const float*)d_in[7];
    const float* a1d = (const float*)d_in[8];
    const float* b1  = (const float*)d_in[9];
    const float* W2  = (const float*)d_in[10];
    const float* a2s = (const float*)d_in[11];
    const float* a2d = (const float*)d_in[12];
    const float* b2  = (const float*)d_in[13];
    const float* hw  = (const float*)d_in[14];
    const float* hb  = (const float*)d_in[15];
    float* out = (float*)d_out;

    int n = in_sizes[0] / 128;
    int E = in_sizes[1] / 2;
    int et = E + n;

    uint32_t* h16;
    float* bufB;
    int* gcursor;
    cudaGetSymbolAddress((void**)&h16, g_h16);
    cudaGetSymbolAddress((void**)&bufB, g_bufB);
    cudaGetSymbolAddress((void**)&gcursor, g_cursor);

    int eblocks = (et + 255) / 256;
    if (eblocks > 4096) eblocks = 4096;
    int nb = (n + 1023) / 1024;
    int gy = (n + 127) / 128;
    int ga4 = (n + 1) / 2;
    int ga1 = (n + 3) / 4;

    int histBlocks = 2048;
    int gemmBlocks = 4 * gy;

    // 0. dtype detection (+ zero pool accumulator)
    detect_kernel<<<1, 64>>>(ei, n);

    // 1. zero histogram
    fill_i32<<<(n + 255) / 256, 256>>>(gcursor, 0, n);

    // 2. GEMM layer 0 fused with edge histogram (independent workloads)
    gemm0_hist<<<gemmBlocks + histBlocks, 256>>>(x, W0, h16, n, a0s, a0d,
                                                 ei, E, gemmBlocks);

    // 3. scan -> rowptr (+cursor), scatter -> CSR
    scan_local<<<nb, 1024>>>(n);
    scan_aux<<<1, 32>>>(nb);
    scan_add<<<nb, 1024>>>(n);
    scatter_kernel<<<eblocks, 256>>>(ei, E, n);

    // ---- Layer 0 aggregate ----
    aggregate4<<<ga4, 128>>>(h16, b0, bufB, n);

    // ---- Layer 1: 256 -> (4,64) ----
    sgemm_tc<<<dim3(4, gy), 256>>>(bufB, W1, h16, n, 256, 256, a1s, a1d, 4);
    aggregate4<<<ga4, 128>>>(h16, b1, bufB, n);

    // ---- Layer 2: 256 -> (1,64) ----
    sgemm_tc<<<dim3(1, gy), 256>>>(bufB, W2, h16, n, 256, 64, a2s, a2d, 1);
    aggregate1<<<ga1, 128>>>(h16, b2, n);   // fuses mean pool

    // ---- Head ----
    head_kernel<<<1, 64>>>(hw, hb, out, n);
}